// round 1
// baseline (speedup 1.0000x reference)
#include <cuda_runtime.h>
#include <math.h>

// ---------------- problem constants ----------------
#define BATCHN  2
#define EDIM    768
#define LTOK    1024          // tokens per window (32x32)
#define BWIN    8             // B*M*N windows
#define NHEADS  8
#define HDIM    96
#define NFREQ   16
#define DFULL   160           // HDIM + 4*NFREQ
#define OUT_ELEMS (BATCHN*EDIM*64*64)   // 6291456 (first output)
// attn output: BWIN*NHEADS*LTOK*LTOK = 67108864 floats, placed after OUT_ELEMS

// ---------------- scratch (static device memory; no allocation) ----------------
__device__ float g_rx [BATCHN*3*1024*1024];      // resized image
__device__ float g_op [BWIN*LTOK*EDIM];          // origin patch tokens (post conv)
__device__ float g_rp [BWIN*LTOK*EDIM];          // resize patch tokens (post conv+pos)
__device__ float g_opn[BWIN*LTOK*EDIM];          // LN(op)
__device__ float g_rpn[BWIN*LTOK*EDIM];          // LN(rp)
__device__ float g_q  [BWIN*LTOK*EDIM];          // q projection
__device__ float g_bv [BWIN*LTOK*EDIM];          // b projection (= tmp_b source)
__device__ float g_qn [BWIN*NHEADS*LTOK*DFULL];  // normalized q+feats
__device__ float g_bn [BWIN*NHEADS*LTOK*DFULL];  // normalized b+feats
__device__ float g_av [BWIN*NHEADS*LTOK*HDIM];   // attn @ tmp_b

// ---------------- 1. bilinear resize 512 -> 1024 (half-pixel centers, clamped) ----------------
__global__ void k_resize(const float* __restrict__ x) {
    int idx = blockIdx.x * blockDim.x + threadIdx.x;
    if (idx >= BATCHN*3*1024*1024) return;
    int ox = idx & 1023;
    int oy = (idx >> 10) & 1023;
    int ch = idx >> 20;                       // b*3+c
    float fy = oy * 0.5f - 0.25f;
    float fx = ox * 0.5f - 0.25f;
    int y0 = (int)floorf(fy); float ty = fy - (float)y0;
    int x0 = (int)floorf(fx); float tx = fx - (float)x0;
    int y1 = y0 + 1, x1 = x0 + 1;
    y0 = max(0, min(511, y0)); y1 = max(0, min(511, y1));
    x0 = max(0, min(511, x0)); x1 = max(0, min(511, x1));
    const float* p = x + (long)ch * 512 * 512;
    float v = p[y0*512+x0]*(1.f-ty)*(1.f-tx) + p[y0*512+x1]*(1.f-ty)*tx
            + p[y1*512+x0]*ty*(1.f-tx)       + p[y1*512+x1]*ty*tx;
    g_rx[idx] = v;
}

// ---------------- 2. origin conv: 8x8 stride 8, groups=3, -> window-token layout ----------------
__global__ void k_conv_o(const float* __restrict__ x, const float* __restrict__ w,
                         const float* __restrict__ bias) {
    __shared__ float patch[192];                  // 3 channels * 64
    int pos = blockIdx.x, b = blockIdx.y;
    int y = pos >> 6, xq = pos & 63;
    int tid = threadIdx.x;                        // 768 threads = 768 out channels
    if (tid < 192) {
        int c = tid >> 6, p = tid & 63, py = p >> 3, px = p & 7;
        patch[tid] = x[(((long)(b*3+c))*512 + y*8+py)*512 + xq*8+px];
    }
    __syncthreads();
    int g = tid >> 8;                             // tid/256
    const float* wp = w + (long)tid * 64;
    const float* pp = patch + g * 64;
    float s = bias[tid];
#pragma unroll
    for (int i = 0; i < 64; i++) s += pp[i] * wp[i];
    int bwn = (b*2 + (y>>5))*2 + (xq>>5);
    int t   = (y&31)*32 + (xq&31);
    g_op[((long)(bwn*LTOK + t))*EDIM + tid] = s;
}

// ---------------- 3. resize conv: 16x16 stride 16, groups=3, + pos_embed ----------------
__global__ void k_conv_r(const float* __restrict__ w, const float* __restrict__ bias,
                         const float* __restrict__ pe) {
    __shared__ float patch[768];                  // 3 channels * 256
    int pos = blockIdx.x, b = blockIdx.y;
    int y = pos >> 6, xq = pos & 63;
    int tid = threadIdx.x;
    {
        int c = tid >> 8, p = tid & 255, py = p >> 4, px = p & 15;
        patch[tid] = g_rx[(((long)(b*3+c))*1024 + y*16+py)*1024 + xq*16+px];
    }
    __syncthreads();
    int g = tid >> 8;
    const float* wp = w + (long)tid * 256;
    const float* pp = patch + g * 256;
    float s = bias[tid] + pe[((long)tid*64 + y)*64 + xq];
#pragma unroll 8
    for (int i = 0; i < 256; i++) s += pp[i] * wp[i];
    int bwn = (b*2 + (y>>5))*2 + (xq>>5);
    int t   = (y&31)*32 + (xq&31);
    g_rp[((long)(bwn*LTOK + t))*EDIM + tid] = s;
}

// ---------------- 4. LayerNorm over 768 (grid.y: 0 = op->opn, 1 = rp->rpn) ----------------
__global__ void k_ln(const float* __restrict__ g0, const float* __restrict__ b0,
                     const float* __restrict__ g1, const float* __restrict__ b1) {
    long row = blockIdx.x;
    const float* in = blockIdx.y ? g_rp : g_op;
    const float* gg = blockIdx.y ? g1 : g0;
    const float* bb = blockIdx.y ? b1 : b0;
    float* out = blockIdx.y ? g_rpn : g_opn;
    const float* r = in + row * EDIM;
    float v[3], s = 0.f, ss = 0.f;
#pragma unroll
    for (int j = 0; j < 3; j++) {
        float xv = r[threadIdx.x + j*256];
        v[j] = xv; s += xv; ss += xv*xv;
    }
    __shared__ float shs[8], shss[8];
    for (int o = 16; o; o >>= 1) {
        s  += __shfl_down_sync(0xffffffffu, s,  o);
        ss += __shfl_down_sync(0xffffffffu, ss, o);
    }
    if ((threadIdx.x & 31) == 0) { shs[threadIdx.x>>5] = s; shss[threadIdx.x>>5] = ss; }
    __syncthreads();
    if (threadIdx.x < 8) {
        s = shs[threadIdx.x]; ss = shss[threadIdx.x];
        for (int o = 4; o; o >>= 1) {
            s  += __shfl_down_sync(0xffu, s,  o);
            ss += __shfl_down_sync(0xffu, ss, o);
        }
        if (threadIdx.x == 0) { shs[0] = s; shss[0] = ss; }
    }
    __syncthreads();
    float mu  = shs[0] * (1.f/768.f);
    float var = shss[0] * (1.f/768.f) - mu*mu;
    float rin = rsqrtf(var + 1e-5f);
#pragma unroll
    for (int j = 0; j < 3; j++) {
        int c = threadIdx.x + j*256;
        out[row*EDIM + c] = (v[j]-mu)*rin*gg[c] + bb[c];
    }
}

// ---------------- generic tiled GEMM: C[M,N] = A[M,K] @ B[N,K]^T (+bias), batched ----------------
// 64x64 tile, 256 threads, 4x4 microtile. M,N multiples of 64; K multiple of 16.
__global__ void gemm_nt(const float* __restrict__ A, const float* __restrict__ B,
                        const float* __restrict__ bias, float* __restrict__ C,
                        int Mt, int Nt, int Kt, long sA, long sB, long sC) {
    A += (long)blockIdx.z * sA;
    B += (long)blockIdx.z * sB;
    C += (long)blockIdx.z * sC;
    __shared__ __align__(16) float As[16][68];
    __shared__ __align__(16) float Bs[16][68];
    int tid = threadIdx.x, tx = tid & 15, ty = tid >> 4;
    int row0 = blockIdx.y * 64, col0 = blockIdx.x * 64;
    float acc[4][4] = {};
    for (int k0 = 0; k0 < Kt; k0 += 16) {
#pragma unroll
        for (int i = tid; i < 1024; i += 256) {
            int kk = i & 15, r = i >> 4;
            As[kk][r] = A[(long)(row0 + r) * Kt + k0 + kk];
        }
#pragma unroll
        for (int i = tid; i < 1024; i += 256) {
            int kk = i & 15, c = i >> 4;
            Bs[kk][c] = B[(long)(col0 + c) * Kt + k0 + kk];
        }
        __syncthreads();
#pragma unroll
        for (int kk = 0; kk < 16; kk++) {
            float4 a4 = *(const float4*)(&As[kk][ty << 2]);
            float4 b4 = *(const float4*)(&Bs[kk][tx << 2]);
            acc[0][0]+=a4.x*b4.x; acc[0][1]+=a4.x*b4.y; acc[0][2]+=a4.x*b4.z; acc[0][3]+=a4.x*b4.w;
            acc[1][0]+=a4.y*b4.x; acc[1][1]+=a4.y*b4.y; acc[1][2]+=a4.y*b4.z; acc[1][3]+=a4.y*b4.w;
            acc[2][0]+=a4.z*b4.x; acc[2][1]+=a4.z*b4.y; acc[2][2]+=a4.z*b4.z; acc[2][3]+=a4.z*b4.w;
            acc[3][0]+=a4.w*b4.x; acc[3][1]+=a4.w*b4.y; acc[3][2]+=a4.w*b4.z; acc[3][3]+=a4.w*b4.w;
        }
        __syncthreads();
    }
#pragma unroll
    for (int i = 0; i < 4; i++) {
        int gr = row0 + (ty << 2) + i;
#pragma unroll
        for (int j = 0; j < 4; j++) {
            int gc = col0 + (tx << 2) + j;
            float vv = acc[i][j];
            if (bias) vv += bias[gc];
            C[(long)gr * Nt + gc] = vv;
        }
    }
}

// ---------------- 5. build normalized q/b rows with RoPE features ----------------
// grid.x = bh*1024 + t  (bh = bw*8 + h), grid.y: 0 = q path, 1 = b path. 160 threads.
__global__ void k_feat() {
    int rowid = blockIdx.x;
    int t  = rowid & 1023;
    int bh = rowid >> 10;
    int h  = bh & 7;
    int bwn = bh >> 3;
    const float* src = blockIdx.y ? g_bv : g_q;
    float* dst       = blockIdx.y ? g_bn : g_qn;
    int tid = threadIdx.x;
    float v;
    if (tid < HDIM) {
        v = src[((long)(bwn*LTOK + t))*EDIM + h*HDIM + tid];
    } else {
        int j = tid - HDIM;
        int grp = j >> 4, f = j & 15;
        float inv = 1.0f / powf(10.0f, (float)f * (1.0f/16.0f));
        float coord = (grp < 2) ? (float)(t & 31) : (float)(t >> 5);
        float ang = coord * inv;
        v = ((grp & 1) == 0) ? cosf(ang) : sinf(ang);
    }
    __shared__ float sh[6];
    float sq = v * v;
    for (int o = 16; o; o >>= 1) sq += __shfl_down_sync(0xffffffffu, sq, o);
    if ((tid & 31) == 0) sh[tid >> 5] = sq;
    __syncthreads();
    if (tid == 0) {
        float s = sh[0] + sh[1] + sh[2] + sh[3] + sh[4];
        sh[5] = 1.0f / fmaxf(sqrtf(s), 1e-12f);
    }
    __syncthreads();
    dst[(long)rowid * DFULL + tid] = v * sh[5];
}

// ---------------- 7. out = attn @ tmp_b  (per bw,head: 1024 x 96 x 1024) ----------------
__global__ void k_av(const float* __restrict__ attn) {
    int z = blockIdx.z;
    int bwn = z >> 3, h = z & 7;
    const float* A  = attn + (long)z * LTOK * LTOK;                 // [i][k], ld = 1024
    const float* Bm = g_bv + (long)bwn * LTOK * EDIM + h * HDIM;    // [k][d], ld = 768
    float* C        = g_av + (long)z * LTOK * HDIM;                 // [i][d], ld = 96
    __shared__ __align__(16) float As[16][68];
    __shared__ __align__(16) float Bs[16][68];
    int tid = threadIdx.x, tx = tid & 15, ty = tid >> 4;
    int row0 = blockIdx.y * 64, col0 = blockIdx.x * 64;
    float acc[4][4] = {};
    for (int k0 = 0; k0 < LTOK; k0 += 16) {
#pragma unroll
        for (int i = tid; i < 1024; i += 256) {
            int kk = i & 15, r = i >> 4;
            As[kk][r] = A[(long)(row0 + r) * LTOK + k0 + kk];
        }
#pragma unroll
        for (int i = tid; i < 1024; i += 256) {
            int cI = i & 63, kk = i >> 6;
            int gc = col0 + cI;
            Bs[kk][cI] = (gc < HDIM) ? Bm[(long)(k0 + kk) * EDIM + gc] : 0.f;
        }
        __syncthreads();
#pragma unroll
        for (int kk = 0; kk < 16; kk++) {
            float4 a4 = *(const float4*)(&As[kk][ty << 2]);
            float4 b4 = *(const float4*)(&Bs[kk][tx << 2]);
            acc[0][0]+=a4.x*b4.x; acc[0][1]+=a4.x*b4.y; acc[0][2]+=a4.x*b4.z; acc[0][3]+=a4.x*b4.w;
            acc[1][0]+=a4.y*b4.x; acc[1][1]+=a4.y*b4.y; acc[1][2]+=a4.y*b4.z; acc[1][3]+=a4.y*b4.w;
            acc[2][0]+=a4.z*b4.x; acc[2][1]+=a4.z*b4.y; acc[2][2]+=a4.z*b4.z; acc[2][3]+=a4.z*b4.w;
            acc[3][0]+=a4.w*b4.x; acc[3][1]+=a4.w*b4.y; acc[3][2]+=a4.w*b4.z; acc[3][3]+=a4.w*b4.w;
        }
        __syncthreads();
    }
#pragma unroll
    for (int i = 0; i < 4; i++) {
        int gr = row0 + (ty << 2) + i;
#pragma unroll
        for (int j = 0; j < 4; j++) {
            int gc = col0 + (tx << 2) + j;
            if (gc < HDIM) C[(long)gr * HDIM + gc] = acc[i][j];
        }
    }
}

// ---------------- 8. final projection with gather (A) and channel-major scatter store ----------
// C[oc][token] = sum_k projw[oc][k] * gather[token][k] + projb[oc]
// token = b*4096 + y*64 + x ; k = h*96 + d ; gather from g_av[(bw*8+h), t, d]
__global__ void k_projf(const float* __restrict__ pw, const float* __restrict__ pb,
                        float* __restrict__ out) {
    __shared__ __align__(16) float As[16][68];
    __shared__ __align__(16) float Bs[16][68];
    int tid = threadIdx.x, tx = tid & 15, ty = tid >> 4;
    int oc0 = blockIdx.y * 64;          // 768 rows
    int tk0 = blockIdx.x * 64;          // 8192 cols (tokens)
    float acc[4][4] = {};
    for (int k0 = 0; k0 < EDIM; k0 += 16) {
#pragma unroll
        for (int i = tid; i < 1024; i += 256) {
            int kk = i & 15, r = i >> 4;
            As[kk][r] = pw[(long)(oc0 + r) * EDIM + k0 + kk];
        }
#pragma unroll
        for (int i = tid; i < 1024; i += 256) {
            int kk = i & 15, c = i >> 4;
            int tok = tk0 + c;
            int k = k0 + kk;
            int b = tok >> 12, p = tok & 4095, y = p >> 6, xq = p & 63;
            int h = k / 96, d = k - h * 96;
            int bwn = (b*2 + (y>>5))*2 + (xq>>5);
            int t = (y&31)*32 + (xq&31);
            Bs[kk][c] = g_av[(((long)(bwn*8 + h))*LTOK + t)*HDIM + d];
        }
        __syncthreads();
#pragma unroll
        for (int kk = 0; kk < 16; kk++) {
            float4 a4 = *(const float4*)(&As[kk][ty << 2]);
            float4 b4 = *(const float4*)(&Bs[kk][tx << 2]);
            acc[0][0]+=a4.x*b4.x; acc[0][1]+=a4.x*b4.y; acc[0][2]+=a4.x*b4.z; acc[0][3]+=a4.x*b4.w;
            acc[1][0]+=a4.y*b4.x; acc[1][1]+=a4.y*b4.y; acc[1][2]+=a4.y*b4.z; acc[1][3]+=a4.y*b4.w;
            acc[2][0]+=a4.z*b4.x; acc[2][1]+=a4.z*b4.y; acc[2][2]+=a4.z*b4.z; acc[2][3]+=a4.z*b4.w;
            acc[3][0]+=a4.w*b4.x; acc[3][1]+=a4.w*b4.y; acc[3][2]+=a4.w*b4.z; acc[3][3]+=a4.w*b4.w;
        }
        __syncthreads();
    }
#pragma unroll
    for (int i = 0; i < 4; i++) {
        int oc = oc0 + (ty << 2) + i;
        float bia = pb[oc];
#pragma unroll
        for (int j = 0; j < 4; j++) {
            int tok = tk0 + (tx << 2) + j;
            int b = tok >> 12, p = tok & 4095;
            out[(long)b * (EDIM*4096) + (long)oc * 4096 + p] = acc[i][j] + bia;
        }
    }
}

// ---------------- host launch ----------------
static float* sym_addr(const void* sym) {
    void* p = nullptr;
    cudaGetSymbolAddress(&p, sym);
    return (float*)p;
}

extern "C" void kernel_launch(void* const* d_in, const int* in_sizes, int n_in,
                              void* d_out, int out_size) {
    const float* x      = (const float*)d_in[0];
    const float* ow     = (const float*)d_in[1];
    const float* obias  = (const float*)d_in[2];
    const float* rw     = (const float*)d_in[3];
    const float* rbias  = (const float*)d_in[4];
    const float* pe     = (const float*)d_in[5];
    const float* nb_g   = (const float*)d_in[6];
    const float* nb_b   = (const float*)d_in[7];
    const float* nq_g   = (const float*)d_in[8];
    const float* nq_b   = (const float*)d_in[9];
    const float* qw     = (const float*)d_in[10];
    const float* qb     = (const float*)d_in[11];
    const float* bw     = (const float*)d_in[12];
    const float* bb     = (const float*)d_in[13];
    const float* projw  = (const float*)d_in[14];
    const float* projb  = (const float*)d_in[15];

    float* out  = (float*)d_out;
    float* attn = out + OUT_ELEMS;

    float* p_rpn = sym_addr(g_rpn);
    float* p_opn = sym_addr(g_opn);
    float* p_q   = sym_addr(g_q);
    float* p_bv  = sym_addr(g_bv);
    float* p_qn  = sym_addr(g_qn);
    float* p_bn  = sym_addr(g_bn);

    // 1. bilinear resize
    k_resize<<<24576, 256>>>(x);
    // 2/3. patch convs -> window-token layout
    k_conv_o<<<dim3(4096, BATCHN), 768>>>(x, ow, obias);
    k_conv_r<<<dim3(4096, BATCHN), 768>>>(rw, rbias, pe);
    // 4. LayerNorms
    k_ln<<<dim3(BWIN*LTOK, 2), 256>>>(nb_g, nb_b, nq_g, nq_b);
    // 5. projections: q = rpn @ qw^T + qb ; b = opn @ bw^T + bb
    gemm_nt<<<dim3(12, 128, 1), 256>>>(p_rpn, qw, qb, p_q,  BWIN*LTOK, EDIM, EDIM, 0, 0, 0);
    gemm_nt<<<dim3(12, 128, 1), 256>>>(p_opn, bw, bb, p_bv, BWIN*LTOK, EDIM, EDIM, 0, 0, 0);
    // 6. per-head rows with RoPE feats + L2 normalize
    k_feat<<<dim3(BWIN*NHEADS*LTOK, 2), DFULL>>>();
    // 7. attn = qn @ bn^T  (64 batched 1024x1024x160) -> second output region
    gemm_nt<<<dim3(16, 16, BWIN*NHEADS), 256>>>(p_qn, p_bn, nullptr, attn,
                                                LTOK, LTOK, DFULL,
                                                (long)LTOK*DFULL, (long)LTOK*DFULL,
                                                (long)LTOK*LTOK);
    // 8. out = attn @ tmp_b  (64 batched 1024x96x1024)
    k_av<<<dim3(2, 16, BWIN*NHEADS), 256>>>(attn);
    // 9. gather + final projection + channel-major store -> first output region
    k_projf<<<dim3(128, 12), 256>>>(projw, projb, out);
}

// round 2
// speedup vs baseline: 4.6686x; 4.6686x over previous
#include <cuda_runtime.h>
#include <math.h>

// ---------------- problem constants ----------------
#define BATCHN  2
#define EDIM    768
#define LTOK    1024
#define BWIN    8
#define NHEADS  8
#define HDIM    96
#define DFULL   160
#define OUT_ELEMS (BATCHN*EDIM*64*64)

// GEMM tiling
#define BM 128
#define BN 128
#define BK 8

// ---------------- scratch ----------------
__device__ float g_rx [BATCHN*3*1024*1024];
__device__ float g_col[BATCHN*3*4096*256];       // im2col for resize conv
__device__ float g_op [BWIN*LTOK*EDIM];
__device__ float g_rp [BWIN*LTOK*EDIM];
__device__ float g_opn[BWIN*LTOK*EDIM];
__device__ float g_rpn[BWIN*LTOK*EDIM];
__device__ float g_q  [BWIN*LTOK*EDIM];
__device__ float g_bv [BWIN*LTOK*EDIM];
__device__ float g_qn [BWIN*NHEADS*LTOK*DFULL];
__device__ float g_bn [BWIN*NHEADS*LTOK*DFULL];
__device__ float g_avt[BATCHN*4096*EDIM];        // attn@b in token-major gathered layout

// ---------------- 1. bilinear resize 512 -> 1024 ----------------
__global__ void k_resize(const float* __restrict__ x) {
    int idx = blockIdx.x * blockDim.x + threadIdx.x;
    if (idx >= BATCHN*3*1024*1024) return;
    int ox = idx & 1023;
    int oy = (idx >> 10) & 1023;
    int ch = idx >> 20;
    float fy = oy * 0.5f - 0.25f;
    float fx = ox * 0.5f - 0.25f;
    int y0 = (int)floorf(fy); float ty = fy - (float)y0;
    int x0 = (int)floorf(fx); float tx = fx - (float)x0;
    int y1 = y0 + 1, x1 = x0 + 1;
    y0 = max(0, min(511, y0)); y1 = max(0, min(511, y1));
    x0 = max(0, min(511, x0)); x1 = max(0, min(511, x1));
    const float* p = x + (long)ch * 512 * 512;
    float v = p[y0*512+x0]*(1.f-ty)*(1.f-tx) + p[y0*512+x1]*(1.f-ty)*tx
            + p[y1*512+x0]*ty*(1.f-tx)       + p[y1*512+x1]*ty*tx;
    g_rx[idx] = v;
}

// ---------------- 2. origin conv: 8x8 stride 8, groups=3 (4 positions/block) ----------------
__global__ void k_conv_o(const float* __restrict__ x, const float* __restrict__ w,
                         const float* __restrict__ bias) {
    __shared__ float patch[4*192];
    int b = blockIdx.y;
    int y  = blockIdx.x >> 4;
    int xg = blockIdx.x & 15;          // group of 4 x positions
    int tid = threadIdx.x;             // 768 threads = out channels
    {
        int p = tid / 192, r = tid % 192;
        int c = r >> 6, pix = r & 63, py = pix >> 3, px = pix & 7;
        patch[tid] = x[(((long)(b*3+c))*512 + y*8+py)*512 + (xg*4+p)*8+px];
    }
    __syncthreads();
    int g = tid >> 8;
    const float* wp = w + (long)tid * 64;
    float s0 = 0.f, s1 = 0.f, s2 = 0.f, s3 = 0.f;
    const float* pp = patch + g * 64;
#pragma unroll
    for (int i = 0; i < 64; i++) {
        float wv = wp[i];
        s0 += wv * pp[i];
        s1 += wv * pp[i + 192];
        s2 += wv * pp[i + 384];
        s3 += wv * pp[i + 576];
    }
    float bia = bias[tid];
#pragma unroll
    for (int p = 0; p < 4; p++) {
        int xq = xg*4 + p;
        int bwn = (b*2 + (y>>5))*2 + (xq>>5);
        int t   = (y&31)*32 + (xq&31);
        float s = (p==0?s0:p==1?s1:p==2?s2:s3) + bia;
        g_op[((long)(bwn*LTOK + t))*EDIM + tid] = s;
    }
}

// ---------------- 3a. im2col for resize conv ----------------
__global__ void k_im2col() {
    long idx = (long)blockIdx.x * blockDim.x + threadIdx.x;
    if (idx >= (long)BATCHN*3*4096*256) return;
    int k   = idx & 255;
    int pos = (idx >> 8) & 4095;
    int z   = idx >> 20;               // b*3+g
    int y = pos >> 6, xq = pos & 63;
    int py = k >> 4, px = k & 15;
    g_col[idx] = g_rx[((long)z*1024 + y*16+py)*1024 + xq*16+px];
}

// ---------------- 4. LayerNorm over 768 ----------------
__global__ void k_ln(const float* __restrict__ g0, const float* __restrict__ b0,
                     const float* __restrict__ g1, const float* __restrict__ b1) {
    long row = blockIdx.x;
    const float* in = blockIdx.y ? g_rp : g_op;
    const float* gg = blockIdx.y ? g1 : g0;
    const float* bb = blockIdx.y ? b1 : b0;
    float* out = blockIdx.y ? g_rpn : g_opn;
    const float* r = in + row * EDIM;
    float v[3], s = 0.f, ss = 0.f;
#pragma unroll
    for (int j = 0; j < 3; j++) {
        float xv = r[threadIdx.x + j*256];
        v[j] = xv; s += xv; ss += xv*xv;
    }
    __shared__ float shs[8], shss[8];
    for (int o = 16; o; o >>= 1) {
        s  += __shfl_down_sync(0xffffffffu, s,  o);
        ss += __shfl_down_sync(0xffffffffu, ss, o);
    }
    if ((threadIdx.x & 31) == 0) { shs[threadIdx.x>>5] = s; shss[threadIdx.x>>5] = ss; }
    __syncthreads();
    if (threadIdx.x < 8) {
        s = shs[threadIdx.x]; ss = shss[threadIdx.x];
        for (int o = 4; o; o >>= 1) {
            s  += __shfl_down_sync(0xffu, s,  o);
            ss += __shfl_down_sync(0xffu, ss, o);
        }
        if (threadIdx.x == 0) { shs[0] = s; shss[0] = ss; }
    }
    __syncthreads();
    float mu  = shs[0] * (1.f/768.f);
    float var = shss[0] * (1.f/768.f) - mu*mu;
    float rin = rsqrtf(var + 1e-5f);
#pragma unroll
    for (int j = 0; j < 3; j++) {
        int c = threadIdx.x + j*256;
        out[row*EDIM + c] = (v[j]-mu)*rin*gg[c] + bb[c];
    }
}

// ---------------- 5. normalized q/b rows with RoPE feats ----------------
__global__ void k_feat() {
    int rowid = blockIdx.x;
    int t  = rowid & 1023;
    int bh = rowid >> 10;
    int h  = bh & 7;
    int bwn = bh >> 3;
    const float* src = blockIdx.y ? g_bv : g_q;
    float* dst       = blockIdx.y ? g_bn : g_qn;
    int tid = threadIdx.x;
    float v;
    if (tid < HDIM) {
        v = src[((long)(bwn*LTOK + t))*EDIM + h*HDIM + tid];
    } else {
        int j = tid - HDIM;
        int grp = j >> 4, f = j & 15;
        float inv = 1.0f / powf(10.0f, (float)f * (1.0f/16.0f));
        float coord = (grp < 2) ? (float)(t & 31) : (float)(t >> 5);
        float ang = coord * inv;
        v = ((grp & 1) == 0) ? cosf(ang) : sinf(ang);
    }
    __shared__ float sh[6];
    float sq = v * v;
    for (int o = 16; o; o >>= 1) sq += __shfl_down_sync(0xffffffffu, sq, o);
    if ((tid & 31) == 0) sh[tid >> 5] = sq;
    __syncthreads();
    if (tid == 0) {
        float s = sh[0] + sh[1] + sh[2] + sh[3] + sh[4];
        sh[5] = 1.0f / fmaxf(sqrtf(s), 1e-12f);
    }
    __syncthreads();
    dst[(long)rowid * DFULL + tid] = v * sh[5];
}

// ================= 128x128 double-buffered fp32 GEMM (NT): C = A[M,K] @ B[N,K]^T =================
// EPI 0: C[row*ldc+col] += bias[col]         (plain / batched)
// EPI 1: resize-conv epilogue -> g_rp (bias + pos_embed + window scatter), z = b*3+g
// EPI 2: final projection -> out[b][oc][pos], bias indexed by row
template<int EPI>
__global__ __launch_bounds__(256, 2)
void gemm_nt_t(const float* __restrict__ A, const float* __restrict__ B,
               const float* __restrict__ bias, float* __restrict__ C,
               int K, int lda, int ldb, int ldc,
               long sA, long sC, long sB,
               const float* __restrict__ pe) {
    __shared__ __align__(16) float As[2][BK][BM+4];
    __shared__ __align__(16) float Bs[2][BK][BN+4];
    long z = blockIdx.z;
    A += z * sA;
    if (EPI == 1) B += (z % 3) * 65536; else B += z * sB;
    if (EPI == 0) C += z * sC;

    int tid = threadIdx.x;
    int tx = tid & 15, ty = tid >> 4;
    int row0 = blockIdx.y * BM, col0 = blockIdx.x * BN;
    int arow = tid >> 1, akq = (tid & 1) * 4;

    const float* Ag = A + (long)(row0 + arow) * lda + akq;
    const float* Bg = B + (long)(col0 + arow) * ldb + akq;

    float4 pa = *(const float4*)Ag;
    float4 pb = *(const float4*)Bg;
    As[0][akq+0][arow]=pa.x; As[0][akq+1][arow]=pa.y; As[0][akq+2][arow]=pa.z; As[0][akq+3][arow]=pa.w;
    Bs[0][akq+0][arow]=pb.x; Bs[0][akq+1][arow]=pb.y; Bs[0][akq+2][arow]=pb.z; Bs[0][akq+3][arow]=pb.w;
    __syncthreads();

    int KT = K / BK;
    float acc[8][8] = {};
    for (int kt = 0; kt < KT; kt++) {
        int cur = kt & 1, nxt = cur ^ 1;
        if (kt + 1 < KT) {
            pa = *(const float4*)(Ag + (long)(kt+1)*BK);
            pb = *(const float4*)(Bg + (long)(kt+1)*BK);
        }
#pragma unroll
        for (int kk = 0; kk < BK; kk++) {
            float4 a0 = *(const float4*)&As[cur][kk][ty*4];
            float4 a1 = *(const float4*)&As[cur][kk][ty*4+64];
            float4 b0 = *(const float4*)&Bs[cur][kk][tx*4];
            float4 b1 = *(const float4*)&Bs[cur][kk][tx*4+64];
            float av[8] = {a0.x,a0.y,a0.z,a0.w,a1.x,a1.y,a1.z,a1.w};
            float bv[8] = {b0.x,b0.y,b0.z,b0.w,b1.x,b1.y,b1.z,b1.w};
#pragma unroll
            for (int i = 0; i < 8; i++)
#pragma unroll
                for (int j = 0; j < 8; j++)
                    acc[i][j] += av[i] * bv[j];
        }
        if (kt + 1 < KT) {
            As[nxt][akq+0][arow]=pa.x; As[nxt][akq+1][arow]=pa.y; As[nxt][akq+2][arow]=pa.z; As[nxt][akq+3][arow]=pa.w;
            Bs[nxt][akq+0][arow]=pb.x; Bs[nxt][akq+1][arow]=pb.y; Bs[nxt][akq+2][arow]=pb.z; Bs[nxt][akq+3][arow]=pb.w;
            __syncthreads();
        }
    }

    if (EPI == 0) {
        float bj[8];
#pragma unroll
        for (int j = 0; j < 8; j++)
            bj[j] = bias ? bias[col0 + tx*4 + (j&3) + ((j>>2)<<6)] : 0.f;
#pragma unroll
        for (int i = 0; i < 8; i++) {
            int row = row0 + ty*4 + (i&3) + ((i>>2)<<6);
            float4 v0 = {acc[i][0]+bj[0], acc[i][1]+bj[1], acc[i][2]+bj[2], acc[i][3]+bj[3]};
            float4 v1 = {acc[i][4]+bj[4], acc[i][5]+bj[5], acc[i][6]+bj[6], acc[i][7]+bj[7]};
            *(float4*)(C + (long)row*ldc + col0 + tx*4)      = v0;
            *(float4*)(C + (long)row*ldc + col0 + tx*4 + 64) = v1;
        }
    } else if (EPI == 1) {
        int b = (int)(z / 3), g = (int)(z % 3);
#pragma unroll
        for (int i = 0; i < 8; i++) {
            int pos = row0 + ty*4 + (i&3) + ((i>>2)<<6);
            int y = pos >> 6, xq = pos & 63;
            int bwn = (b*2 + (y>>5))*2 + (xq>>5);
            int t   = (y&31)*32 + (xq&31);
            float* dst = g_rp + ((long)(bwn*LTOK + t))*EDIM + g*256;
#pragma unroll
            for (int jh = 0; jh < 2; jh++) {
                int c0 = col0 + tx*4 + jh*64;
                float4 v;
                v.x = acc[i][jh*4+0] + bias[g*256+c0+0] + pe[(long)(g*256+c0+0)*4096 + pos];
                v.y = acc[i][jh*4+1] + bias[g*256+c0+1] + pe[(long)(g*256+c0+1)*4096 + pos];
                v.z = acc[i][jh*4+2] + bias[g*256+c0+2] + pe[(long)(g*256+c0+2)*4096 + pos];
                v.w = acc[i][jh*4+3] + bias[g*256+c0+3] + pe[(long)(g*256+c0+3)*4096 + pos];
                *(float4*)(dst + c0) = v;
            }
        }
    } else { // EPI == 2: C = out, row = oc, col = token
#pragma unroll
        for (int i = 0; i < 8; i++) {
            int oc = row0 + ty*4 + (i&3) + ((i>>2)<<6);
            float bia = bias[oc];
#pragma unroll
            for (int jh = 0; jh < 2; jh++) {
                int tok = col0 + tx*4 + jh*64;
                int b = tok >> 12, p = tok & 4095;
                float4 v = {acc[i][jh*4+0]+bia, acc[i][jh*4+1]+bia,
                            acc[i][jh*4+2]+bia, acc[i][jh*4+3]+bia};
                *(float4*)(C + (long)b*(EDIM*4096) + (long)oc*4096 + p) = v;
            }
        }
    }
}

// ================= attn @ tmp_b (NN): per z=(bwn,h): [1024 x 96] = attn[1024,1024] @ b[1024,96] ==
__global__ __launch_bounds__(256, 2)
void gemm_nn_av(const float* __restrict__ attn) {
    __shared__ __align__(16) float As[2][BK][BM+4];
    __shared__ __align__(16) float Bs[2][BK][BN+4];
    int z = blockIdx.z;
    int bwn = z >> 3, h = z & 7;
    const float* A  = attn + (long)z * LTOK * LTOK;
    const float* Bg0 = g_bv + (long)bwn * LTOK * EDIM + h * HDIM;   // [k][d], ld 768

    int tid = threadIdx.x;
    int tx = tid & 15, ty = tid >> 4;
    int row0 = blockIdx.y * BM;
    int arow = tid >> 1, akq = (tid & 1) * 4;
    const float* Ag = A + (long)(row0 + arow) * LTOK + akq;
    int bkk = tid >> 5, bc4 = (tid & 31) * 4;

    float4 pa = *(const float4*)Ag;
    float4 pb = (bc4 < HDIM) ? *(const float4*)(Bg0 + (long)bkk*EDIM + bc4)
                             : make_float4(0.f,0.f,0.f,0.f);
    As[0][akq+0][arow]=pa.x; As[0][akq+1][arow]=pa.y; As[0][akq+2][arow]=pa.z; As[0][akq+3][arow]=pa.w;
    *(float4*)&Bs[0][bkk][bc4] = pb;
    __syncthreads();

    const int KT = LTOK / BK;
    float acc[8][8] = {};
    for (int kt = 0; kt < KT; kt++) {
        int cur = kt & 1, nxt = cur ^ 1;
        if (kt + 1 < KT) {
            pa = *(const float4*)(Ag + (long)(kt+1)*BK);
            pb = (bc4 < HDIM) ? *(const float4*)(Bg0 + (long)((kt+1)*BK + bkk)*EDIM + bc4)
                              : make_float4(0.f,0.f,0.f,0.f);
        }
#pragma unroll
        for (int kk = 0; kk < BK; kk++) {
            float4 a0 = *(const float4*)&As[cur][kk][ty*4];
            float4 a1 = *(const float4*)&As[cur][kk][ty*4+64];
            float4 b0 = *(const float4*)&Bs[cur][kk][tx*4];
            float4 b1 = *(const float4*)&Bs[cur][kk][tx*4+64];
            float av[8] = {a0.x,a0.y,a0.z,a0.w,a1.x,a1.y,a1.z,a1.w};
            float bv[8] = {b0.x,b0.y,b0.z,b0.w,b1.x,b1.y,b1.z,b1.w};
#pragma unroll
            for (int i = 0; i < 8; i++)
#pragma unroll
                for (int j = 0; j < 8; j++)
                    acc[i][j] += av[i] * bv[j];
        }
        if (kt + 1 < KT) {
            As[nxt][akq+0][arow]=pa.x; As[nxt][akq+1][arow]=pa.y; As[nxt][akq+2][arow]=pa.z; As[nxt][akq+3][arow]=pa.w;
            *(float4*)&Bs[nxt][bkk][bc4] = pb;
            __syncthreads();
        }
    }

    // scatter to token-major gathered layout g_avt[b*4096 + gy*64 + gx][h*96 + d]
    int b  = bwn >> 2, wy = (bwn >> 1) & 1, wx = bwn & 1;
#pragma unroll
    for (int i = 0; i < 8; i++) {
        int t = row0 + ty*4 + (i&3) + ((i>>2)<<6);      // token within window
        int ly = t >> 5, lx = t & 31;
        int tok = b*4096 + (wy*32+ly)*64 + (wx*32+lx);
        float* dst = g_avt + (long)tok*EDIM + h*HDIM;
#pragma unroll
        for (int jh = 0; jh < 2; jh++) {
            int d = tx*4 + jh*64;
            if (d < HDIM) {
                float4 v = {acc[i][jh*4+0], acc[i][jh*4+1], acc[i][jh*4+2], acc[i][jh*4+3]};
                *(float4*)(dst + d) = v;
            }
        }
    }
}

// ---------------- host launch ----------------
static float* sym_addr(const void* sym) {
    void* p = nullptr;
    cudaGetSymbolAddress(&p, sym);
    return (float*)p;
}

extern "C" void kernel_launch(void* const* d_in, const int* in_sizes, int n_in,
                              void* d_out, int out_size) {
    const float* x      = (const float*)d_in[0];
    const float* ow     = (const float*)d_in[1];
    const float* obias  = (const float*)d_in[2];
    const float* rw     = (const float*)d_in[3];
    const float* rbias  = (const float*)d_in[4];
    const float* pe     = (const float*)d_in[5];
    const float* nb_g   = (const float*)d_in[6];
    const float* nb_b   = (const float*)d_in[7];
    const float* nq_g   = (const float*)d_in[8];
    const float* nq_b   = (const float*)d_in[9];
    const float* qw     = (const float*)d_in[10];
    const float* qb     = (const float*)d_in[11];
    const float* bw     = (const float*)d_in[12];
    const float* bb     = (const float*)d_in[13];
    const float* projw  = (const float*)d_in[14];
    const float* projb  = (const float*)d_in[15];

    float* out  = (float*)d_out;
    float* attn = out + OUT_ELEMS;

    float* p_col = sym_addr(g_col);
    float* p_rpn = sym_addr(g_rpn);
    float* p_opn = sym_addr(g_opn);
    float* p_q   = sym_addr(g_q);
    float* p_bv  = sym_addr(g_bv);
    float* p_qn  = sym_addr(g_qn);
    float* p_bn  = sym_addr(g_bn);
    float* p_avt = sym_addr(g_avt);

    // 1. resize + origin conv + im2col
    k_resize<<<24576, 256>>>(x);
    k_conv_o<<<dim3(1024, BATCHN), 768>>>(x, ow, obias);
    k_im2col<<<24576, 256>>>();
    // 2. resize conv as GEMM (M=4096 pos, N=256 oc, K=256), z = b*3+g, epilogue -> g_rp
    gemm_nt_t<1><<<dim3(2, 32, 6), 256>>>(p_col, rw, rbias, nullptr,
                                          256, 256, 256, 0,
                                          (long)4096*256, 0, 0, pe);
    // 3. LayerNorms
    k_ln<<<dim3(BWIN*LTOK, 2), 256>>>(nb_g, nb_b, nq_g, nq_b);
    // 4. projections (M=8192, N=768, K=768)
    gemm_nt_t<0><<<dim3(6, 64, 1), 256>>>(p_rpn, qw, qb, p_q,
                                          EDIM, EDIM, EDIM, EDIM, 0, 0, 0, nullptr);
    gemm_nt_t<0><<<dim3(6, 64, 1), 256>>>(p_opn, bw, bb, p_bv,
                                          EDIM, EDIM, EDIM, EDIM, 0, 0, 0, nullptr);
    // 5. per-head rows with RoPE feats + L2 normalize
    k_feat<<<dim3(BWIN*NHEADS*LTOK, 2), DFULL>>>();
    // 6. attn = qn @ bn^T (batched z=64: 1024x1024x160) -> second output region
    gemm_nt_t<0><<<dim3(8, 8, BWIN*NHEADS), 256>>>(p_qn, p_bn, nullptr, attn,
                                                   DFULL, DFULL, DFULL, LTOK,
                                                   (long)LTOK*DFULL, (long)LTOK*LTOK,
                                                   (long)LTOK*DFULL, nullptr);
    // 7. out_v = attn @ tmp_b -> token-major gathered layout
    gemm_nn_av<<<dim3(1, 8, BWIN*NHEADS), 256>>>(attn);
    // 8. final projection (M=768 oc, N=8192 tok, K=768) -> first output region
    gemm_nt_t<2><<<dim3(64, 6, 1), 256>>>(projw, p_avt, projb, out,
                                          EDIM, EDIM, EDIM, 0, 0, 0, 0, nullptr);
}

// round 4
// speedup vs baseline: 6.0649x; 1.2991x over previous
#include <cuda_runtime.h>
#include <math.h>
#include <stdint.h>

// ---------------- problem constants ----------------
#define BATCHN  2
#define EDIM    768
#define LTOK    1024
#define BWIN    8
#define NHEADS  8
#define HDIM    96
#define DFULL   160
#define OUT_ELEMS (BATCHN*EDIM*64*64)

// ---------------- scratch ----------------
__device__ float g_rx [BATCHN*3*1024*1024];
__device__ float g_col[BATCHN*3*4096*256];
__device__ float g_op [BWIN*LTOK*EDIM];
__device__ float g_rp [BWIN*LTOK*EDIM];
__device__ float g_opn[BWIN*LTOK*EDIM];
__device__ float g_rpn[BWIN*LTOK*EDIM];
__device__ float g_q  [BWIN*LTOK*EDIM];
__device__ float g_bv [BWIN*LTOK*EDIM];
__device__ float g_qn [BWIN*NHEADS*LTOK*DFULL];
__device__ float g_bn [BWIN*NHEADS*LTOK*DFULL];
__device__ float g_avt[BATCHN*4096*EDIM];
__device__ float g_bvt[BWIN*NHEADS*HDIM*LTOK];   // per z transposed b: [d][t]
__device__ float g_pet[4096*EDIM];               // pos_embed transposed: [pos][c]

// ---------------- 1. bilinear resize 512 -> 1024 ----------------
__global__ void k_resize(const float* __restrict__ x) {
    int idx = blockIdx.x * blockDim.x + threadIdx.x;
    if (idx >= BATCHN*3*1024*1024) return;
    int ox = idx & 1023;
    int oy = (idx >> 10) & 1023;
    int ch = idx >> 20;
    float fy = oy * 0.5f - 0.25f;
    float fx = ox * 0.5f - 0.25f;
    int y0 = (int)floorf(fy); float ty = fy - (float)y0;
    int x0 = (int)floorf(fx); float tx = fx - (float)x0;
    int y1 = y0 + 1, x1 = x0 + 1;
    y0 = max(0, min(511, y0)); y1 = max(0, min(511, y1));
    x0 = max(0, min(511, x0)); x1 = max(0, min(511, x1));
    const float* p = x + (long)ch * 512 * 512;
    float v = p[y0*512+x0]*(1.f-ty)*(1.f-tx) + p[y0*512+x1]*(1.f-ty)*tx
            + p[y1*512+x0]*ty*(1.f-tx)       + p[y1*512+x1]*ty*tx;
    g_rx[idx] = v;
}

// ---------------- 2. origin conv ----------------
__global__ void k_conv_o(const float* __restrict__ x, const float* __restrict__ w,
                         const float* __restrict__ bias) {
    __shared__ float patch[4*192];
    int b = blockIdx.y;
    int y  = blockIdx.x >> 4;
    int xg = blockIdx.x & 15;
    int tid = threadIdx.x;
    {
        int p = tid / 192, r = tid % 192;
        int c = r >> 6, pix = r & 63, py = pix >> 3, px = pix & 7;
        patch[tid] = x[(((long)(b*3+c))*512 + y*8+py)*512 + (xg*4+p)*8+px];
    }
    __syncthreads();
    int g = tid >> 8;
    const float* wp = w + (long)tid * 64;
    float s0 = 0.f, s1 = 0.f, s2 = 0.f, s3 = 0.f;
    const float* pp = patch + g * 64;
#pragma unroll
    for (int i = 0; i < 64; i++) {
        float wv = wp[i];
        s0 += wv * pp[i];
        s1 += wv * pp[i + 192];
        s2 += wv * pp[i + 384];
        s3 += wv * pp[i + 576];
    }
    float bia = bias[tid];
#pragma unroll
    for (int p = 0; p < 4; p++) {
        int xq = xg*4 + p;
        int bwn = (b*2 + (y>>5))*2 + (xq>>5);
        int t   = (y&31)*32 + (xq&31);
        float s = (p==0?s0:p==1?s1:p==2?s2:s3) + bia;
        g_op[((long)(bwn*LTOK + t))*EDIM + tid] = s;
    }
}

// ---------------- 3. im2col ----------------
__global__ void k_im2col() {
    long idx = (long)blockIdx.x * blockDim.x + threadIdx.x;
    if (idx >= (long)BATCHN*3*4096*256) return;
    int k   = idx & 255;
    int pos = (idx >> 8) & 4095;
    int z   = idx >> 20;
    int y = pos >> 6, xq = pos & 63;
    int py = k >> 4, px = k & 15;
    g_col[idx] = g_rx[((long)z*1024 + y*16+py)*1024 + xq*16+px];
}

// ---------------- 4. LayerNorm ----------------
__global__ void k_ln(const float* __restrict__ g0, const float* __restrict__ b0,
                     const float* __restrict__ g1, const float* __restrict__ b1) {
    long row = blockIdx.x;
    const float* in = blockIdx.y ? g_rp : g_op;
    const float* gg = blockIdx.y ? g1 : g0;
    const float* bb = blockIdx.y ? b1 : b0;
    float* out = blockIdx.y ? g_rpn : g_opn;
    const float* r = in + row * EDIM;
    float v[3], s = 0.f, ss = 0.f;
#pragma unroll
    for (int j = 0; j < 3; j++) {
        float xv = r[threadIdx.x + j*256];
        v[j] = xv; s += xv; ss += xv*xv;
    }
    __shared__ float shs[8], shss[8];
    for (int o = 16; o; o >>= 1) {
        s  += __shfl_down_sync(0xffffffffu, s,  o);
        ss += __shfl_down_sync(0xffffffffu, ss, o);
    }
    if ((threadIdx.x & 31) == 0) { shs[threadIdx.x>>5] = s; shss[threadIdx.x>>5] = ss; }
    __syncthreads();
    if (threadIdx.x < 8) {
        s = shs[threadIdx.x]; ss = shss[threadIdx.x];
        for (int o = 4; o; o >>= 1) {
            s  += __shfl_down_sync(0xffu, s,  o);
            ss += __shfl_down_sync(0xffu, ss, o);
        }
        if (threadIdx.x == 0) { shs[0] = s; shss[0] = ss; }
    }
    __syncthreads();
    float mu  = shs[0] * (1.f/768.f);
    float var = shss[0] * (1.f/768.f) - mu*mu;
    float rin = rsqrtf(var + 1e-5f);
#pragma unroll
    for (int j = 0; j < 3; j++) {
        int c = threadIdx.x + j*256;
        out[row*EDIM + c] = (v[j]-mu)*rin*gg[c] + bb[c];
    }
}

// ---------------- 5. normalized q/b rows with RoPE feats ----------------
__global__ void k_feat() {
    int rowid = blockIdx.x;
    int t  = rowid & 1023;
    int bh = rowid >> 10;
    int h  = bh & 7;
    int bwn = bh >> 3;
    const float* src = blockIdx.y ? g_bv : g_q;
    float* dst       = blockIdx.y ? g_bn : g_qn;
    int tid = threadIdx.x;
    float v;
    if (tid < HDIM) {
        v = src[((long)(bwn*LTOK + t))*EDIM + h*HDIM + tid];
    } else {
        int j = tid - HDIM;
        int grp = j >> 4, f = j & 15;
        float inv = 1.0f / powf(10.0f, (float)f * (1.0f/16.0f));
        float coord = (grp < 2) ? (float)(t & 31) : (float)(t >> 5);
        float ang = coord * inv;
        v = ((grp & 1) == 0) ? cosf(ang) : sinf(ang);
    }
    __shared__ float sh[6];
    float sq = v * v;
    for (int o = 16; o; o >>= 1) sq += __shfl_down_sync(0xffffffffu, sq, o);
    if ((tid & 31) == 0) sh[tid >> 5] = sq;
    __syncthreads();
    if (tid == 0) {
        float s = sh[0] + sh[1] + sh[2] + sh[3] + sh[4];
        sh[5] = 1.0f / fmaxf(sqrtf(s), 1e-12f);
    }
    __syncthreads();
    dst[(long)rowid * DFULL + tid] = v * sh[5];
}

// ---------------- 6a. transpose b per (bwn,h): [t][d] -> [d][t] ----------------
__global__ void k_tr_bv() {
    __shared__ float s[32][33];
    int z = blockIdx.z; int bwn = z >> 3, h = z & 7;
    int d0 = blockIdx.x * 32, t0 = blockIdx.y * 32;
    int tx = threadIdx.x, ty = threadIdx.y;
#pragma unroll
    for (int j = 0; j < 4; j++) {
        int t = t0 + ty*4 + j;
        s[ty*4+j][tx] = g_bv[((long)(bwn*LTOK + t))*EDIM + h*HDIM + d0 + tx];
    }
    __syncthreads();
#pragma unroll
    for (int j = 0; j < 4; j++) {
        int d = d0 + ty*4 + j;
        g_bvt[((long)(z*HDIM + d))*LTOK + t0 + tx] = s[tx][ty*4+j];
    }
}

// ---------------- 6b. transpose pos_embed: [c][pos] -> [pos][c] ----------------
__global__ void k_tr_pe(const float* __restrict__ pe) {
    __shared__ float s[32][33];
    int c0 = blockIdx.x * 32, p0 = blockIdx.y * 32;
    int tx = threadIdx.x, ty = threadIdx.y;
#pragma unroll
    for (int j = 0; j < 4; j++)
        s[ty*4+j][tx] = pe[(long)(c0 + ty*4 + j)*4096 + p0 + tx];
    __syncthreads();
#pragma unroll
    for (int j = 0; j < 4; j++)
        g_pet[(long)(p0 + ty*4 + j)*EDIM + c0 + tx] = s[tx][ty*4+j];
}

// ================= tf32 mma.sync GEMM (NT): C[M,N] = A[M,K] @ B[N,K]^T =================
// 128x128 CTA tile, BK=32, 8 warps (2x4 -> warp tile 64x32), m16n8k8 tf32 mma.
// EPI 0: plain (+bias by col), batched
// EPI 1: conv-r epilogue -> g_rp (bias+pe+window scatter), z = b*3+g
// EPI 2: final projection -> out[b][oc][pos], bias by row
// EPI 3: av epilogue -> g_avt token-major scatter (cols<96), z = bwn*8+h
#define LDT  132                 // padded row stride (floats) of [BK][128] tiles
#define BUFF (32*LDT)            // 4224 floats per tile buffer
#define SMEMSZ (4*BUFF*4)        // A0,A1,B0,B1 = 67584 bytes

__device__ __forceinline__ uint32_t f2tf32(float f) {
    uint32_t u;
    asm("cvt.rna.tf32.f32 %0, %1;" : "=r"(u) : "f"(f));
    return u;
}
__device__ __forceinline__ void mma8(float* d, const uint32_t* a, const uint32_t* b) {
    asm volatile(
        "mma.sync.aligned.m16n8k8.row.col.f32.tf32.tf32.f32 "
        "{%0,%1,%2,%3}, {%4,%5,%6,%7}, {%8,%9}, {%0,%1,%2,%3};"
        : "+f"(d[0]), "+f"(d[1]), "+f"(d[2]), "+f"(d[3])
        : "r"(a[0]), "r"(a[1]), "r"(a[2]), "r"(a[3]), "r"(b[0]), "r"(b[1]));
}

template<int EPI>
__global__ __launch_bounds__(256)
void tc_gemm(const float* __restrict__ A, const float* __restrict__ B,
             const float* __restrict__ bias, float* __restrict__ C,
             int K, int lda, int ldb, int ldc, int nB,
             long sA, long sB, long sC) {
    extern __shared__ __align__(16) float sm[];
    int tid = threadIdx.x;
    int wid = tid >> 5, lane = tid & 31;
    int tg = lane >> 2, t4 = lane & 3;
    long z = blockIdx.z;
    A += z * sA;
    if (EPI == 1) B += (z % 3) * 65536; else B += z * sB;
    if (EPI == 0) C += z * sC;

    int row0 = blockIdx.y * 128, col0 = blockIdx.x * 128;
    int wm = wid >> 2, wn = wid & 3;           // 2 x 4 warps
    int m_base = wm * 64, n_base = wn * 32;

    float acc[4][4][4] = {};                   // [im][in][reg]
    const int KT = K >> 5;

    // per-thread load coords (16 A floats + 16 B floats per chunk)
    int lr[4], lc[4];
#pragma unroll
    for (int p = 0; p < 4; p++) {
        int i2 = tid + p*256;
        lr[p] = i2 >> 3;
        lc[p] = (i2 & 7) << 2;
    }

    // preload chunk 0
    float4 pa[4], pb[4];
#pragma unroll
    for (int p = 0; p < 4; p++) {
        pa[p] = *(const float4*)(A + (long)(row0 + lr[p])*lda + lc[p]);
        pb[p] = (col0 + lr[p] < nB)
              ? *(const float4*)(B + (long)(col0 + lr[p])*ldb + lc[p])
              : make_float4(0.f,0.f,0.f,0.f);
    }
#pragma unroll
    for (int p = 0; p < 4; p++) {
        float* as = sm + 0*BUFF + lr[p];
        float* bs = sm + 2*BUFF + lr[p];
        as[(lc[p]+0)*LDT] = __uint_as_float(f2tf32(pa[p].x));
        as[(lc[p]+1)*LDT] = __uint_as_float(f2tf32(pa[p].y));
        as[(lc[p]+2)*LDT] = __uint_as_float(f2tf32(pa[p].z));
        as[(lc[p]+3)*LDT] = __uint_as_float(f2tf32(pa[p].w));
        bs[(lc[p]+0)*LDT] = __uint_as_float(f2tf32(pb[p].x));
        bs[(lc[p]+1)*LDT] = __uint_as_float(f2tf32(pb[p].y));
        bs[(lc[p]+2)*LDT] = __uint_as_float(f2tf32(pb[p].z));
        bs[(lc[p]+3)*LDT] = __uint_as_float(f2tf32(pb[p].w));
    }
    __syncthreads();

    for (int kt = 0; kt < KT; kt++) {
        int cur = kt & 1, nxt = cur ^ 1;
        if (kt + 1 < KT) {
            int k0 = (kt + 1) << 5;
#pragma unroll
            for (int p = 0; p < 4; p++) {
                pa[p] = *(const float4*)(A + (long)(row0 + lr[p])*lda + k0 + lc[p]);
                pb[p] = (col0 + lr[p] < nB)
                      ? *(const float4*)(B + (long)(col0 + lr[p])*ldb + k0 + lc[p])
                      : make_float4(0.f,0.f,0.f,0.f);
            }
        }
        const float* As = sm + cur*BUFF;
        const float* Bs = sm + 2*BUFF + cur*BUFF;
#pragma unroll
        for (int ks = 0; ks < 4; ks++) {
            int kk = ks*8 + t4;
            uint32_t af[4][4], bf[4][2];
            const float* Ar0 = As + kk*LDT     + m_base + tg;
            const float* Ar1 = As + (kk+4)*LDT + m_base + tg;
            const float* Br0 = Bs + kk*LDT     + n_base + tg;
            const float* Br1 = Bs + (kk+4)*LDT + n_base + tg;
#pragma unroll
            for (int im = 0; im < 4; im++) {
                af[im][0] = __float_as_uint(Ar0[im*16]);
                af[im][1] = __float_as_uint(Ar0[im*16 + 8]);
                af[im][2] = __float_as_uint(Ar1[im*16]);
                af[im][3] = __float_as_uint(Ar1[im*16 + 8]);
            }
#pragma unroll
            for (int in = 0; in < 4; in++) {
                bf[in][0] = __float_as_uint(Br0[in*8]);
                bf[in][1] = __float_as_uint(Br1[in*8]);
            }
#pragma unroll
            for (int im = 0; im < 4; im++)
#pragma unroll
                for (int in = 0; in < 4; in++)
                    mma8(acc[im][in], af[im], bf[in]);
        }
        if (kt + 1 < KT) {
            __syncthreads();
#pragma unroll
            for (int p = 0; p < 4; p++) {
                float* as = sm + nxt*BUFF + lr[p];
                float* bs = sm + 2*BUFF + nxt*BUFF + lr[p];
                as[(lc[p]+0)*LDT] = __uint_as_float(f2tf32(pa[p].x));
                as[(lc[p]+1)*LDT] = __uint_as_float(f2tf32(pa[p].y));
                as[(lc[p]+2)*LDT] = __uint_as_float(f2tf32(pa[p].z));
                as[(lc[p]+3)*LDT] = __uint_as_float(f2tf32(pa[p].w));
                bs[(lc[p]+0)*LDT] = __uint_as_float(f2tf32(pb[p].x));
                bs[(lc[p]+1)*LDT] = __uint_as_float(f2tf32(pb[p].y));
                bs[(lc[p]+2)*LDT] = __uint_as_float(f2tf32(pb[p].z));
                bs[(lc[p]+3)*LDT] = __uint_as_float(f2tf32(pb[p].w));
            }
            __syncthreads();
        }
    }

    // stage C through smem (reuse tile region), xor-swizzled float4 slots
    __syncthreads();
#pragma unroll
    for (int im = 0; im < 4; im++) {
#pragma unroll
        for (int in = 0; in < 4; in++) {
            int r = m_base + im*16 + tg;
            int c = n_base + in*8 + t4*2;
            int s0 = ((c >> 2) ^ (r & 31));
            float* p0 = sm + (r << 7) + (s0 << 2) + (c & 3);
            p0[0] = acc[im][in][0]; p0[1] = acc[im][in][1];
            int r2 = r + 8;
            int s2 = ((c >> 2) ^ (r2 & 31));
            float* p2 = sm + (r2 << 7) + (s2 << 2) + (c & 3);
            p2[0] = acc[im][in][2]; p2[1] = acc[im][in][3];
        }
    }
    __syncthreads();

    // coalesced global stores with epilogue
#pragma unroll 1
    for (int pass = 0; pass < 16; pass++) {
        int r  = pass*8 + wid;
        int c4 = lane;
        int slot = c4 ^ (r & 31);
        float4 v = *(const float4*)(sm + (r << 7) + (slot << 2));
        int row = row0 + r;
        int col = col0 + (c4 << 2);
        if (EPI == 0) {
            if (bias) { v.x += bias[col]; v.y += bias[col+1]; v.z += bias[col+2]; v.w += bias[col+3]; }
            *(float4*)(C + (long)row*ldc + col) = v;
        } else if (EPI == 1) {
            int pos = row;
            int y = pos >> 6, xq = pos & 63;
            int bb_ = (int)(z / 3), g = (int)(z % 3);
            int bwn = (bb_*2 + (y>>5))*2 + (xq>>5);
            int t   = (y&31)*32 + (xq&31);
            int cc  = g*256 + col;
            float4 pb4 = *(const float4*)(g_pet + (long)pos*EDIM + cc);
            v.x += bias[cc+0] + pb4.x; v.y += bias[cc+1] + pb4.y;
            v.z += bias[cc+2] + pb4.z; v.w += bias[cc+3] + pb4.w;
            *(float4*)(g_rp + ((long)(bwn*LTOK + t))*EDIM + cc) = v;
        } else if (EPI == 2) {
            int oc = row, tok = col;
            int bb_ = tok >> 12, p = tok & 4095;
            float bia = bias[oc];
            v.x += bia; v.y += bia; v.z += bia; v.w += bia;
            *(float4*)(C + (long)bb_*(EDIM*4096) + (long)oc*4096 + p) = v;
        } else { // EPI 3
            if (c4 < 24) {
                int bwn = (int)(z >> 3), h = (int)(z & 7);
                int t = row;
                int b_ = bwn >> 2, wy = (bwn >> 1) & 1, wx = bwn & 1;
                int ly = t >> 5, lx = t & 31;
                int tok = b_*4096 + (wy*32 + ly)*64 + (wx*32 + lx);
                *(float4*)(g_avt + (long)tok*EDIM + h*HDIM + (c4 << 2)) = v;
            }
        }
    }
}

// ---------------- host launch ----------------
static float* sym_addr(const void* sym) {
    void* p = nullptr;
    cudaGetSymbolAddress(&p, sym);
    return (float*)p;
}

extern "C" void kernel_launch(void* const* d_in, const int* in_sizes, int n_in,
                              void* d_out, int out_size) {
    const float* x      = (const float*)d_in[0];
    const float* ow     = (const float*)d_in[1];
    const float* obias  = (const float*)d_in[2];
    const float* rw     = (const float*)d_in[3];
    const float* rbias  = (const float*)d_in[4];
    const float* pe     = (const float*)d_in[5];
    const float* nb_g   = (const float*)d_in[6];
    const float* nb_b   = (const float*)d_in[7];
    const float* nq_g   = (const float*)d_in[8];
    const float* nq_b   = (const float*)d_in[9];
    const float* qw     = (const float*)d_in[10];
    const float* qb     = (const float*)d_in[11];
    const float* bw     = (const float*)d_in[12];
    const float* bb     = (const float*)d_in[13];
    const float* projw  = (const float*)d_in[14];
    const float* projb  = (const float*)d_in[15];

    float* out  = (float*)d_out;
    float* attn = out + OUT_ELEMS;

    float* p_col = sym_addr(g_col);
    float* p_rpn = sym_addr(g_rpn);
    float* p_opn = sym_addr(g_opn);
    float* p_q   = sym_addr(g_q);
    float* p_bv  = sym_addr(g_bv);
    float* p_qn  = sym_addr(g_qn);
    float* p_bn  = sym_addr(g_bn);
    float* p_avt = sym_addr(g_avt);
    float* p_bvt = sym_addr(g_bvt);

    cudaFuncSetAttribute(tc_gemm<0>, cudaFuncAttributeMaxDynamicSharedMemorySize, SMEMSZ);
    cudaFuncSetAttribute(tc_gemm<1>, cudaFuncAttributeMaxDynamicSharedMemorySize, SMEMSZ);
    cudaFuncSetAttribute(tc_gemm<2>, cudaFuncAttributeMaxDynamicSharedMemorySize, SMEMSZ);
    cudaFuncSetAttribute(tc_gemm<3>, cudaFuncAttributeMaxDynamicSharedMemorySize, SMEMSZ);

    // 1. resize + origin conv + im2col + pe transpose
    k_resize<<<24576, 256>>>(x);
    k_conv_o<<<dim3(1024, BATCHN), 768>>>(x, ow, obias);
    k_im2col<<<24576, 256>>>();
    k_tr_pe<<<dim3(24, 128), dim3(32, 8)>>>(pe);
    // 2. resize conv as tf32 GEMM (M=4096, N=256, K=256), z = b*3+g -> g_rp
    tc_gemm<1><<<dim3(2, 32, 6), 256, SMEMSZ>>>(p_col, rw, rbias, nullptr,
                                                256, 256, 256, 0, 256,
                                                (long)4096*256, 0, 0);
    // 3. LayerNorms
    k_ln<<<dim3(BWIN*LTOK, 2), 256>>>(nb_g, nb_b, nq_g, nq_b);
    // 4. projections (M=8192, N=768, K=768)
    tc_gemm<0><<<dim3(6, 64, 1), 256, SMEMSZ>>>(p_rpn, qw, qb, p_q,
                                                EDIM, EDIM, EDIM, EDIM, EDIM, 0, 0, 0);
    tc_gemm<0><<<dim3(6, 64, 1), 256, SMEMSZ>>>(p_opn, bw, bb, p_bv,
                                                EDIM, EDIM, EDIM, EDIM, EDIM, 0, 0, 0);
    // 5. RoPE feats + L2 normalize; transpose b for AV
    k_feat<<<dim3(BWIN*NHEADS*LTOK, 2), DFULL>>>();
    k_tr_bv<<<dim3(3, 32, 64), dim3(32, 8)>>>();
    // 6. attn = qn @ bn^T (z=64: 1024x1024x160) -> second output region
    tc_gemm<0><<<dim3(8, 8, BWIN*NHEADS), 256, SMEMSZ>>>(p_qn, p_bn, nullptr, attn,
                                                         DFULL, DFULL, DFULL, LTOK, LTOK,
                                                         (long)LTOK*DFULL, (long)LTOK*DFULL,
                                                         (long)LTOK*LTOK);
    // 7. av = attn @ b (z=64: 1024x96(pad 128)x1024) -> g_avt
    tc_gemm<3><<<dim3(1, 8, BWIN*NHEADS), 256, SMEMSZ>>>(attn, p_bvt, nullptr, nullptr,
                                                         LTOK, LTOK, LTOK, 0, HDIM,
                                                         (long)LTOK*LTOK, (long)HDIM*LTOK, 0);
    // 8. final projection (M=768 oc, N=8192 tok, K=768) -> first output region
    tc_gemm<2><<<dim3(64, 6, 1), 256, SMEMSZ>>>(projw, p_avt, projb, out,
                                                EDIM, EDIM, EDIM, 0, 8192, 0, 0, 0);
}

// round 5
// speedup vs baseline: 6.4252x; 1.0594x over previous
#include <cuda_runtime.h>
#include <math.h>
#include <stdint.h>

// ---------------- problem constants ----------------
#define BATCHN  2
#define EDIM    768
#define LTOK    1024
#define BWIN    8
#define NHEADS  8
#define HDIM    96
#define OUT_ELEMS (BATCHN*EDIM*64*64)

// ---------------- scratch ----------------
__device__ float g_rx [BATCHN*3*1024*1024];
__device__ float g_col[BATCHN*3*4096*256];
__device__ float g_op [BWIN*LTOK*EDIM];
__device__ float g_rp [BWIN*LTOK*EDIM];
__device__ float g_opn[BWIN*LTOK*EDIM];
__device__ float g_rpn[BWIN*LTOK*EDIM];
__device__ float g_q  [BWIN*LTOK*EDIM];
__device__ float g_bv [BWIN*LTOK*EDIM];
__device__ float g_avt[BATCHN*4096*EDIM];
__device__ float g_bvt[BWIN*NHEADS*HDIM*LTOK];   // per z transposed b: [d][t]
__device__ float g_pet[4096*EDIM];               // pos_embed transposed: [pos][c]
__device__ float g_inq[BWIN*NHEADS*LTOK];        // 1/norm for q rows
__device__ float g_inb[BWIN*NHEADS*LTOK];        // 1/norm for b rows
__device__ float g_G  [64];                      // RoPE delta table G[d+31]

// ---------------- 1. bilinear resize 512 -> 1024 ----------------
__global__ void k_resize(const float* __restrict__ x) {
    int idx = blockIdx.x * blockDim.x + threadIdx.x;
    if (idx >= BATCHN*3*1024*1024) return;
    int ox = idx & 1023;
    int oy = (idx >> 10) & 1023;
    int ch = idx >> 20;
    float fy = oy * 0.5f - 0.25f;
    float fx = ox * 0.5f - 0.25f;
    int y0 = (int)floorf(fy); float ty = fy - (float)y0;
    int x0 = (int)floorf(fx); float tx = fx - (float)x0;
    int y1 = y0 + 1, x1 = x0 + 1;
    y0 = max(0, min(511, y0)); y1 = max(0, min(511, y1));
    x0 = max(0, min(511, x0)); x1 = max(0, min(511, x1));
    const float* p = x + (long)ch * 512 * 512;
    float v = p[y0*512+x0]*(1.f-ty)*(1.f-tx) + p[y0*512+x1]*(1.f-ty)*tx
            + p[y1*512+x0]*ty*(1.f-tx)       + p[y1*512+x1]*ty*tx;
    g_rx[idx] = v;
}

// ---------------- 2. origin conv ----------------
__global__ void k_conv_o(const float* __restrict__ x, const float* __restrict__ w,
                         const float* __restrict__ bias) {
    __shared__ float patch[4*192];
    int b = blockIdx.y;
    int y  = blockIdx.x >> 4;
    int xg = blockIdx.x & 15;
    int tid = threadIdx.x;
    {
        int p = tid / 192, r = tid % 192;
        int c = r >> 6, pix = r & 63, py = pix >> 3, px = pix & 7;
        patch[tid] = x[(((long)(b*3+c))*512 + y*8+py)*512 + (xg*4+p)*8+px];
    }
    __syncthreads();
    int g = tid >> 8;
    const float* wp = w + (long)tid * 64;
    float s0 = 0.f, s1 = 0.f, s2 = 0.f, s3 = 0.f;
    const float* pp = patch + g * 64;
#pragma unroll
    for (int i = 0; i < 64; i++) {
        float wv = wp[i];
        s0 += wv * pp[i];
        s1 += wv * pp[i + 192];
        s2 += wv * pp[i + 384];
        s3 += wv * pp[i + 576];
    }
    float bia = bias[tid];
#pragma unroll
    for (int p = 0; p < 4; p++) {
        int xq = xg*4 + p;
        int bwn = (b*2 + (y>>5))*2 + (xq>>5);
        int t   = (y&31)*32 + (xq&31);
        float s = (p==0?s0:p==1?s1:p==2?s2:s3) + bia;
        g_op[((long)(bwn*LTOK + t))*EDIM + tid] = s;
    }
}

// ---------------- 3. im2col ----------------
__global__ void k_im2col() {
    long idx = (long)blockIdx.x * blockDim.x + threadIdx.x;
    if (idx >= (long)BATCHN*3*4096*256) return;
    int k   = idx & 255;
    int pos = (idx >> 8) & 4095;
    int z   = idx >> 20;
    int y = pos >> 6, xq = pos & 63;
    int py = k >> 4, px = k & 15;
    g_col[idx] = g_rx[((long)z*1024 + y*16+py)*1024 + xq*16+px];
}

// ---------------- 4. LayerNorm ----------------
__global__ void k_ln(const float* __restrict__ g0, const float* __restrict__ b0,
                     const float* __restrict__ g1, const float* __restrict__ b1) {
    long row = blockIdx.x;
    const float* in = blockIdx.y ? g_rp : g_op;
    const float* gg = blockIdx.y ? g1 : g0;
    const float* bb = blockIdx.y ? b1 : b0;
    float* out = blockIdx.y ? g_rpn : g_opn;
    const float* r = in + row * EDIM;
    float v[3], s = 0.f, ss = 0.f;
#pragma unroll
    for (int j = 0; j < 3; j++) {
        float xv = r[threadIdx.x + j*256];
        v[j] = xv; s += xv; ss += xv*xv;
    }
    __shared__ float shs[8], shss[8];
    for (int o = 16; o; o >>= 1) {
        s  += __shfl_down_sync(0xffffffffu, s,  o);
        ss += __shfl_down_sync(0xffffffffu, ss, o);
    }
    if ((threadIdx.x & 31) == 0) { shs[threadIdx.x>>5] = s; shss[threadIdx.x>>5] = ss; }
    __syncthreads();
    if (threadIdx.x < 8) {
        s = shs[threadIdx.x]; ss = shss[threadIdx.x];
        for (int o = 4; o; o >>= 1) {
            s  += __shfl_down_sync(0xffu, s,  o);
            ss += __shfl_down_sync(0xffu, ss, o);
        }
        if (threadIdx.x == 0) { shs[0] = s; shss[0] = ss; }
    }
    __syncthreads();
    float mu  = shs[0] * (1.f/768.f);
    float var = shss[0] * (1.f/768.f) - mu*mu;
    float rin = rsqrtf(var + 1e-5f);
#pragma unroll
    for (int j = 0; j < 3; j++) {
        int c = threadIdx.x + j*256;
        out[row*EDIM + c] = (v[j]-mu)*rin*gg[c] + bb[c];
    }
}

// ---------------- 5a. RoPE delta table: G[d+31] = sum_f cos(d * 10^{-f/16}) ----------------
__global__ void k_gtab() {
    int tid = threadIdx.x;
    if (tid < 63) {
        float d = (float)(tid - 31);
        float s = 0.f;
#pragma unroll
        for (int f = 0; f < 16; f++)
            s += cosf(d * powf(10.0f, -(float)f / 16.0f));
        g_G[tid] = s;
    }
}

// ---------------- 5b. per-row inverse norms: 1/sqrt(|q96|^2 + 32) ----------------
__global__ void k_norm() {
    int z = blockIdx.x;                 // bwn*8 + h
    int bwn = z >> 3, h = z & 7;
    const float* src = blockIdx.y ? g_bv : g_q;
    float* dst       = blockIdx.y ? g_inb : g_inq;
    int wid = threadIdx.x >> 5, lane = threadIdx.x & 31;
    for (int t = wid; t < LTOK; t += 8) {
        const float* r = src + ((long)(bwn*LTOK + t))*EDIM + h*HDIM;
        float s = 0.f;
#pragma unroll
        for (int j = 0; j < 3; j++) {
            float v = r[lane + 32*j];
            s += v*v;
        }
        for (int o = 16; o; o >>= 1) s += __shfl_down_sync(0xffffffffu, s, o);
        if (lane == 0) dst[z*LTOK + t] = rsqrtf(s + 32.0f);
    }
}

// ---------------- 6a. transpose b per (bwn,h): [t][d] -> [d][t] ----------------
__global__ void k_tr_bv() {
    __shared__ float s[32][33];
    int z = blockIdx.z; int bwn = z >> 3, h = z & 7;
    int d0 = blockIdx.x * 32, t0 = blockIdx.y * 32;
    int tx = threadIdx.x, ty = threadIdx.y;
#pragma unroll
    for (int j = 0; j < 4; j++) {
        int t = t0 + ty*4 + j;
        s[ty*4+j][tx] = g_bv[((long)(bwn*LTOK + t))*EDIM + h*HDIM + d0 + tx];
    }
    __syncthreads();
#pragma unroll
    for (int j = 0; j < 4; j++) {
        int d = d0 + ty*4 + j;
        g_bvt[((long)(z*HDIM + d))*LTOK + t0 + tx] = s[tx][ty*4+j];
    }
}

// ---------------- 6b. transpose pos_embed: [c][pos] -> [pos][c] ----------------
__global__ void k_tr_pe(const float* __restrict__ pe) {
    __shared__ float s[32][33];
    int c0 = blockIdx.x * 32, p0 = blockIdx.y * 32;
    int tx = threadIdx.x, ty = threadIdx.y;
#pragma unroll
    for (int j = 0; j < 4; j++)
        s[ty*4+j][tx] = pe[(long)(c0 + ty*4 + j)*4096 + p0 + tx];
    __syncthreads();
#pragma unroll
    for (int j = 0; j < 4; j++)
        g_pet[(long)(p0 + ty*4 + j)*EDIM + c0 + tx] = s[tx][ty*4+j];
}

// ================= tf32 mma.sync GEMM (NT): C[M,N] = A[M,K] @ B[N,K]^T =================
// 128 x (32*NMMA) CTA tile, BK=32, 8 warps (2x4), warp tile 64 x (8*NMMA).
// EPI 0: plain (+bias by col), batched
// EPI 1: conv-r epilogue -> g_rp (bias+pe+window scatter), z = b*3+g
// EPI 2: final projection -> out[b][oc][pos], bias by row
// EPI 3: av epilogue -> g_avt token-major scatter, NMMA=3 (N=96), z = bwn*8+h
// EPI 4: attn epilogue: (S + G[dx]+G[dy]) * inq[row] * inb[col], A/B per-head slices
#define LDT  132
#define BUFF (32*LDT)
#define SMEMSZ (4*BUFF*4)

__device__ __forceinline__ uint32_t f2tf32(float f) {
    uint32_t u;
    asm("cvt.rna.tf32.f32 %0, %1;" : "=r"(u) : "f"(f));
    return u;
}
__device__ __forceinline__ void mma8(float* d, const uint32_t* a, const uint32_t* b) {
    asm volatile(
        "mma.sync.aligned.m16n8k8.row.col.f32.tf32.tf32.f32 "
        "{%0,%1,%2,%3}, {%4,%5,%6,%7}, {%8,%9}, {%0,%1,%2,%3};"
        : "+f"(d[0]), "+f"(d[1]), "+f"(d[2]), "+f"(d[3])
        : "r"(a[0]), "r"(a[1]), "r"(a[2]), "r"(a[3]), "r"(b[0]), "r"(b[1]));
}

template<int EPI, int NMMA>
__global__ __launch_bounds__(256)
void tc_gemm(const float* __restrict__ A, const float* __restrict__ B,
             const float* __restrict__ bias, float* __restrict__ C,
             int K, int lda, int ldb, int ldc,
             long sA, long sB, long sC,
             const float* __restrict__ sr, const float* __restrict__ sc) {
    extern __shared__ __align__(16) float sm[];
    int tid = threadIdx.x;
    int wid = tid >> 5, lane = tid & 31;
    int tg = lane >> 2, t4 = lane & 3;
    long z = blockIdx.z;
    if (EPI == 4) {
        long off = (z >> 3) * (long)LTOK * EDIM + (z & 7) * HDIM;
        A += off; B += off;
        C += z * sC;
    } else {
        A += z * sA;
        if (EPI == 1) B += (z % 3) * 65536; else B += z * sB;
        if (EPI == 0) C += z * sC;
    }

    int row0 = blockIdx.y * 128, col0 = blockIdx.x * (32*NMMA);
    int wm = wid >> 2, wn = wid & 3;
    int m_base = wm * 64, n_base = wn * (8*NMMA);

    float acc[4][NMMA][4] = {};
    const int KT = K >> 5;

    int lr[4], lc[4];
#pragma unroll
    for (int p = 0; p < 4; p++) {
        int i2 = tid + p*256;
        lr[p] = i2 >> 3;
        lc[p] = (i2 & 7) << 2;
    }

    float4 pa[4], pb[NMMA];
#pragma unroll
    for (int p = 0; p < 4; p++)
        pa[p] = *(const float4*)(A + (long)(row0 + lr[p])*lda + lc[p]);
#pragma unroll
    for (int p = 0; p < NMMA; p++)
        pb[p] = *(const float4*)(B + (long)(col0 + lr[p])*ldb + lc[p]);
#pragma unroll
    for (int p = 0; p < 4; p++) {
        float* as = sm + lr[p];
        as[(lc[p]+0)*LDT] = __uint_as_float(f2tf32(pa[p].x));
        as[(lc[p]+1)*LDT] = __uint_as_float(f2tf32(pa[p].y));
        as[(lc[p]+2)*LDT] = __uint_as_float(f2tf32(pa[p].z));
        as[(lc[p]+3)*LDT] = __uint_as_float(f2tf32(pa[p].w));
    }
#pragma unroll
    for (int p = 0; p < NMMA; p++) {
        float* bs = sm + 2*BUFF + lr[p];
        bs[(lc[p]+0)*LDT] = __uint_as_float(f2tf32(pb[p].x));
        bs[(lc[p]+1)*LDT] = __uint_as_float(f2tf32(pb[p].y));
        bs[(lc[p]+2)*LDT] = __uint_as_float(f2tf32(pb[p].z));
        bs[(lc[p]+3)*LDT] = __uint_as_float(f2tf32(pb[p].w));
    }
    __syncthreads();

    for (int kt = 0; kt < KT; kt++) {
        int cur = kt & 1, nxt = cur ^ 1;
        if (kt + 1 < KT) {
            int k0 = (kt + 1) << 5;
#pragma unroll
            for (int p = 0; p < 4; p++)
                pa[p] = *(const float4*)(A + (long)(row0 + lr[p])*lda + k0 + lc[p]);
#pragma unroll
            for (int p = 0; p < NMMA; p++)
                pb[p] = *(const float4*)(B + (long)(col0 + lr[p])*ldb + k0 + lc[p]);
        }
        const float* As = sm + cur*BUFF;
        const float* Bs = sm + 2*BUFF + cur*BUFF;
#pragma unroll
        for (int ks = 0; ks < 4; ks++) {
            int kk = ks*8 + t4;
            uint32_t af[4][4], bf[NMMA][2];
            const float* Ar0 = As + kk*LDT     + m_base + tg;
            const float* Ar1 = As + (kk+4)*LDT + m_base + tg;
            const float* Br0 = Bs + kk*LDT     + n_base + tg;
            const float* Br1 = Bs + (kk+4)*LDT + n_base + tg;
#pragma unroll
            for (int im = 0; im < 4; im++) {
                af[im][0] = __float_as_uint(Ar0[im*16]);
                af[im][1] = __float_as_uint(Ar0[im*16 + 8]);
                af[im][2] = __float_as_uint(Ar1[im*16]);
                af[im][3] = __float_as_uint(Ar1[im*16 + 8]);
            }
#pragma unroll
            for (int in = 0; in < NMMA; in++) {
                bf[in][0] = __float_as_uint(Br0[in*8]);
                bf[in][1] = __float_as_uint(Br1[in*8]);
            }
#pragma unroll
            for (int im = 0; im < 4; im++)
#pragma unroll
                for (int in = 0; in < NMMA; in++)
                    mma8(acc[im][in], af[im], bf[in]);
        }
        if (kt + 1 < KT) {
            __syncthreads();
#pragma unroll
            for (int p = 0; p < 4; p++) {
                float* as = sm + nxt*BUFF + lr[p];
                as[(lc[p]+0)*LDT] = __uint_as_float(f2tf32(pa[p].x));
                as[(lc[p]+1)*LDT] = __uint_as_float(f2tf32(pa[p].y));
                as[(lc[p]+2)*LDT] = __uint_as_float(f2tf32(pa[p].z));
                as[(lc[p]+3)*LDT] = __uint_as_float(f2tf32(pa[p].w));
            }
#pragma unroll
            for (int p = 0; p < NMMA; p++) {
                float* bs = sm + 2*BUFF + nxt*BUFF + lr[p];
                bs[(lc[p]+0)*LDT] = __uint_as_float(f2tf32(pb[p].x));
                bs[(lc[p]+1)*LDT] = __uint_as_float(f2tf32(pb[p].y));
                bs[(lc[p]+2)*LDT] = __uint_as_float(f2tf32(pb[p].z));
                bs[(lc[p]+3)*LDT] = __uint_as_float(f2tf32(pb[p].w));
            }
            __syncthreads();
        }
    }

    // stage C through smem, xor-swizzled float4 slots; load G table for EPI 4
    __syncthreads();
    if (EPI == 4 && tid < 63) sm[16448 + tid] = g_G[tid];
#pragma unroll
    for (int im = 0; im < 4; im++) {
#pragma unroll
        for (int in = 0; in < NMMA; in++) {
            int r = m_base + im*16 + tg;
            int c = n_base + in*8 + t4*2;
            int s0 = ((c >> 2) ^ (r & 31));
            float* p0 = sm + (r << 7) + (s0 << 2) + (c & 3);
            p0[0] = acc[im][in][0]; p0[1] = acc[im][in][1];
            int r2 = r + 8;
            int s2 = ((c >> 2) ^ (r2 & 31));
            float* p2 = sm + (r2 << 7) + (s2 << 2) + (c & 3);
            p2[0] = acc[im][in][2]; p2[1] = acc[im][in][3];
        }
    }
    __syncthreads();

#pragma unroll 1
    for (int pass = 0; pass < 16; pass++) {
        int r  = pass*8 + wid;
        int c4 = lane;
        if (NMMA == 3 && c4 >= 24) continue;
        int slot = c4 ^ (r & 31);
        float4 v = *(const float4*)(sm + (r << 7) + (slot << 2));
        int row = row0 + r;
        int col = col0 + (c4 << 2);
        if (EPI == 0) {
            if (bias) { v.x += bias[col]; v.y += bias[col+1]; v.z += bias[col+2]; v.w += bias[col+3]; }
            *(float4*)(C + (long)row*ldc + col) = v;
        } else if (EPI == 1) {
            int pos = row;
            int y = pos >> 6, xq = pos & 63;
            int bb_ = (int)(z / 3), g = (int)(z % 3);
            int bwn = (bb_*2 + (y>>5))*2 + (xq>>5);
            int t   = (y&31)*32 + (xq&31);
            int cc  = g*256 + col;
            float4 pb4 = *(const float4*)(g_pet + (long)pos*EDIM + cc);
            v.x += bias[cc+0] + pb4.x; v.y += bias[cc+1] + pb4.y;
            v.z += bias[cc+2] + pb4.z; v.w += bias[cc+3] + pb4.w;
            *(float4*)(g_rp + ((long)(bwn*LTOK + t))*EDIM + cc) = v;
        } else if (EPI == 2) {
            int oc = row, tok = col;
            int bb_ = tok >> 12, p = tok & 4095;
            float bia = bias[oc];
            v.x += bia; v.y += bia; v.z += bia; v.w += bia;
            *(float4*)(C + (long)bb_*(EDIM*4096) + (long)oc*4096 + p) = v;
        } else if (EPI == 3) {
            int bwn = (int)(z >> 3), h = (int)(z & 7);
            int t = row;
            int b_ = bwn >> 2, wy = (bwn >> 1) & 1, wx = bwn & 1;
            int ly = t >> 5, lx = t & 31;
            int tok = b_*4096 + (wy*32 + ly)*64 + (wx*32 + lx);
            *(float4*)(g_avt + (long)tok*EDIM + h*HDIM + (c4 << 2)) = v;
        } else { // EPI 4: attn epilogue
            const float* smG = sm + 16448;
            int xi = row & 31, yi = row >> 5;
            float iq = sr[z*LTOK + row];
            float4 ib4 = *(const float4*)(sc + z*LTOK + col);
            int xj0 = col & 31, yj0 = col >> 5;
            // col..col+3 within same 32-token row segment? col%32 in {0..28}, +3 stays<32 ✓
            v.x = (v.x + smG[xi - xj0     + 31] + smG[yi - yj0 + 31]) * iq * ib4.x;
            v.y = (v.y + smG[xi - (xj0+1) + 31] + smG[yi - yj0 + 31]) * iq * ib4.y;
            v.z = (v.z + smG[xi - (xj0+2) + 31] + smG[yi - yj0 + 31]) * iq * ib4.z;
            v.w = (v.w + smG[xi - (xj0+3) + 31] + smG[yi - yj0 + 31]) * iq * ib4.w;
            *(float4*)(C + (long)row*ldc + col) = v;
        }
    }
}

// ---------------- host launch ----------------
static float* sym_addr(const void* sym) {
    void* p = nullptr;
    cudaGetSymbolAddress(&p, sym);
    return (float*)p;
}

extern "C" void kernel_launch(void* const* d_in, const int* in_sizes, int n_in,
                              void* d_out, int out_size) {
    const float* x      = (const float*)d_in[0];
    const float* ow     = (const float*)d_in[1];
    const float* obias  = (const float*)d_in[2];
    const float* rw     = (const float*)d_in[3];
    const float* rbias  = (const float*)d_in[4];
    const float* pe     = (const float*)d_in[5];
    const float* nb_g   = (const float*)d_in[6];
    const float* nb_b   = (const float*)d_in[7];
    const float* nq_g   = (const float*)d_in[8];
    const float* nq_b   = (const float*)d_in[9];
    const float* qw     = (const float*)d_in[10];
    const float* qb     = (const float*)d_in[11];
    const float* bw     = (const float*)d_in[12];
    const float* bb     = (const float*)d_in[13];
    const float* projw  = (const float*)d_in[14];
    const float* projb  = (const float*)d_in[15];

    float* out  = (float*)d_out;
    float* attn = out + OUT_ELEMS;

    float* p_col = sym_addr(g_col);
    float* p_rpn = sym_addr(g_rpn);
    float* p_opn = sym_addr(g_opn);
    float* p_q   = sym_addr(g_q);
    float* p_bv  = sym_addr(g_bv);
    float* p_avt = sym_addr(g_avt);
    float* p_bvt = sym_addr(g_bvt);
    float* p_inq = sym_addr(g_inq);
    float* p_inb = sym_addr(g_inb);

    cudaFuncSetAttribute(tc_gemm<0,4>, cudaFuncAttributeMaxDynamicSharedMemorySize, SMEMSZ);
    cudaFuncSetAttribute(tc_gemm<1,4>, cudaFuncAttributeMaxDynamicSharedMemorySize, SMEMSZ);
    cudaFuncSetAttribute(tc_gemm<2,4>, cudaFuncAttributeMaxDynamicSharedMemorySize, SMEMSZ);
    cudaFuncSetAttribute(tc_gemm<3,3>, cudaFuncAttributeMaxDynamicSharedMemorySize, SMEMSZ);
    cudaFuncSetAttribute(tc_gemm<4,4>, cudaFuncAttributeMaxDynamicSharedMemorySize, SMEMSZ);

    // 1. resize + origin conv + im2col + pe transpose + G table
    k_resize<<<24576, 256>>>(x);
    k_conv_o<<<dim3(1024, BATCHN), 768>>>(x, ow, obias);
    k_im2col<<<24576, 256>>>();
    k_tr_pe<<<dim3(24, 128), dim3(32, 8)>>>(pe);
    k_gtab<<<1, 64>>>();
    // 2. resize conv as tf32 GEMM (M=4096, N=256, K=256), z = b*3+g -> g_rp
    tc_gemm<1,4><<<dim3(2, 32, 6), 256, SMEMSZ>>>(p_col, rw, rbias, nullptr,
                                                  256, 256, 256, 0,
                                                  (long)4096*256, 0, 0, nullptr, nullptr);
    // 3. LayerNorms
    k_ln<<<dim3(BWIN*LTOK, 2), 256>>>(nb_g, nb_b, nq_g, nq_b);
    // 4. projections (M=8192, N=768, K=768)
    tc_gemm<0,4><<<dim3(6, 64, 1), 256, SMEMSZ>>>(p_rpn, qw, qb, p_q,
                                                  EDIM, EDIM, EDIM, EDIM, 0, 0, 0, nullptr, nullptr);
    tc_gemm<0,4><<<dim3(6, 64, 1), 256, SMEMSZ>>>(p_opn, bw, bb, p_bv,
                                                  EDIM, EDIM, EDIM, EDIM, 0, 0, 0, nullptr, nullptr);
    // 5. inverse norms + b transpose
    k_norm<<<dim3(BWIN*NHEADS, 2), 256>>>();
    k_tr_bv<<<dim3(3, 32, 64), dim3(32, 8)>>>();
    // 6. attn = (q96·b96 + G) * inq * inb  (z=64: 1024x1024x96) -> second output region
    tc_gemm<4,4><<<dim3(8, 8, BWIN*NHEADS), 256, SMEMSZ>>>(p_q, p_bv, nullptr, attn,
                                                           HDIM, EDIM, EDIM, LTOK,
                                                           0, 0, (long)LTOK*LTOK,
                                                           p_inq, p_inb);
    // 7. av = attn @ b (z=64: 1024x96x1024, exact N=96) -> g_avt
    tc_gemm<3,3><<<dim3(1, 8, BWIN*NHEADS), 256, SMEMSZ>>>(attn, p_bvt, nullptr, nullptr,
                                                           LTOK, LTOK, LTOK, 0,
                                                           (long)LTOK*LTOK, (long)HDIM*LTOK, 0,
                                                           nullptr, nullptr);
    // 8. final projection (M=768 oc, N=8192 tok, K=768) -> first output region
    tc_gemm<2,4><<<dim3(64, 6, 1), 256, SMEMSZ>>>(projw, p_avt, projb, out,
                                                  EDIM, EDIM, EDIM, 0, 0, 0, 0,
                                                  nullptr, nullptr);
}

// round 6
// speedup vs baseline: 7.9600x; 1.2389x over previous
#include <cuda_runtime.h>
#include <math.h>
#include <stdint.h>

// ---------------- problem constants ----------------
#define BATCHN  2
#define EDIM    768
#define LTOK    1024
#define BWIN    8
#define NHEADS  8
#define HDIM    96
#define OUT_ELEMS (BATCHN*EDIM*64*64)

// ---------------- scratch ----------------
__device__ float g_rx [BATCHN*3*1024*1024];
__device__ float g_op [BWIN*LTOK*EDIM];
__device__ float g_rp [BWIN*LTOK*EDIM];
__device__ float g_opn[BWIN*LTOK*EDIM];
__device__ float g_rpn[BWIN*LTOK*EDIM];
__device__ float g_q  [BWIN*LTOK*EDIM];
__device__ float g_bv [BWIN*LTOK*EDIM];
__device__ float g_avt[BATCHN*4096*EDIM];
__device__ float g_bvt[BWIN*NHEADS*HDIM*LTOK];   // per z transposed b: [d][t]
__device__ float g_pet[4096*EDIM];               // pos_embed transposed: [pos][c]
__device__ float g_inq[BWIN*NHEADS*LTOK];
__device__ float g_inb[BWIN*NHEADS*LTOK];
__device__ float g_G  [64];

// ---------------- bilinear resize 512 -> 1024 ----------------
__global__ void k_resize(const float* __restrict__ x) {
    int idx = blockIdx.x * blockDim.x + threadIdx.x;
    if (idx >= BATCHN*3*1024*1024) return;
    int ox = idx & 1023;
    int oy = (idx >> 10) & 1023;
    int ch = idx >> 20;
    float fy = oy * 0.5f - 0.25f;
    float fx = ox * 0.5f - 0.25f;
    int y0 = (int)floorf(fy); float ty = fy - (float)y0;
    int x0 = (int)floorf(fx); float tx = fx - (float)x0;
    int y1 = y0 + 1, x1 = x0 + 1;
    y0 = max(0, min(511, y0)); y1 = max(0, min(511, y1));
    x0 = max(0, min(511, x0)); x1 = max(0, min(511, x1));
    const float* p = x + (long)ch * 512 * 512;
    float v = p[y0*512+x0]*(1.f-ty)*(1.f-tx) + p[y0*512+x1]*(1.f-ty)*tx
            + p[y1*512+x0]*ty*(1.f-tx)       + p[y1*512+x1]*ty*tx;
    g_rx[idx] = v;
}

// ---------------- origin conv ----------------
__global__ void k_conv_o(const float* __restrict__ x, const float* __restrict__ w,
                         const float* __restrict__ bias) {
    __shared__ float patch[4*192];
    int b = blockIdx.y;
    int y  = blockIdx.x >> 4;
    int xg = blockIdx.x & 15;
    int tid = threadIdx.x;
    {
        int p = tid / 192, r = tid % 192;
        int c = r >> 6, pix = r & 63, py = pix >> 3, px = pix & 7;
        patch[tid] = x[(((long)(b*3+c))*512 + y*8+py)*512 + (xg*4+p)*8+px];
    }
    __syncthreads();
    int g = tid >> 8;
    const float* wp = w + (long)tid * 64;
    float s0 = 0.f, s1 = 0.f, s2 = 0.f, s3 = 0.f;
    const float* pp = patch + g * 64;
#pragma unroll
    for (int i = 0; i < 64; i++) {
        float wv = wp[i];
        s0 += wv * pp[i];
        s1 += wv * pp[i + 192];
        s2 += wv * pp[i + 384];
        s3 += wv * pp[i + 576];
    }
    float bia = bias[tid];
#pragma unroll
    for (int p = 0; p < 4; p++) {
        int xq = xg*4 + p;
        int bwn = (b*2 + (y>>5))*2 + (xq>>5);
        int t   = (y&31)*32 + (xq&31);
        float s = (p==0?s0:p==1?s1:p==2?s2:s3) + bia;
        g_op[((long)(bwn*LTOK + t))*EDIM + tid] = s;
    }
}

// ---------------- LayerNorm ----------------
__global__ void k_ln(const float* __restrict__ g0, const float* __restrict__ b0,
                     const float* __restrict__ g1, const float* __restrict__ b1) {
    long row = blockIdx.x;
    const float* in = blockIdx.y ? g_rp : g_op;
    const float* gg = blockIdx.y ? g1 : g0;
    const float* bb = blockIdx.y ? b1 : b0;
    float* out = blockIdx.y ? g_rpn : g_opn;
    const float* r = in + row * EDIM;
    float v[3], s = 0.f, ss = 0.f;
#pragma unroll
    for (int j = 0; j < 3; j++) {
        float xv = r[threadIdx.x + j*256];
        v[j] = xv; s += xv; ss += xv*xv;
    }
    __shared__ float shs[8], shss[8];
    for (int o = 16; o; o >>= 1) {
        s  += __shfl_down_sync(0xffffffffu, s,  o);
        ss += __shfl_down_sync(0xffffffffu, ss, o);
    }
    if ((threadIdx.x & 31) == 0) { shs[threadIdx.x>>5] = s; shss[threadIdx.x>>5] = ss; }
    __syncthreads();
    if (threadIdx.x < 8) {
        s = shs[threadIdx.x]; ss = shss[threadIdx.x];
        for (int o = 4; o; o >>= 1) {
            s  += __shfl_down_sync(0xffu, s,  o);
            ss += __shfl_down_sync(0xffu, ss, o);
        }
        if (threadIdx.x == 0) { shs[0] = s; shss[0] = ss; }
    }
    __syncthreads();
    float mu  = shs[0] * (1.f/768.f);
    float var = shss[0] * (1.f/768.f) - mu*mu;
    float rin = rsqrtf(var + 1e-5f);
#pragma unroll
    for (int j = 0; j < 3; j++) {
        int c = threadIdx.x + j*256;
        out[row*EDIM + c] = (v[j]-mu)*rin*gg[c] + bb[c];
    }
}

// ---------------- RoPE delta table ----------------
__global__ void k_gtab() {
    int tid = threadIdx.x;
    if (tid < 63) {
        float d = (float)(tid - 31);
        float s = 0.f;
#pragma unroll
        for (int f = 0; f < 16; f++)
            s += cosf(d * powf(10.0f, -(float)f / 16.0f));
        g_G[tid] = s;
    }
}

// ---------------- per-row inverse norms ----------------
__global__ void k_norm() {
    int z = blockIdx.x;
    int bwn = z >> 3, h = z & 7;
    const float* src = blockIdx.y ? g_bv : g_q;
    float* dst       = blockIdx.y ? g_inb : g_inq;
    int wid = threadIdx.x >> 5, lane = threadIdx.x & 31;
    for (int t = wid; t < LTOK; t += 8) {
        const float* r = src + ((long)(bwn*LTOK + t))*EDIM + h*HDIM;
        float s = 0.f;
#pragma unroll
        for (int j = 0; j < 3; j++) {
            float v = r[lane + 32*j];
            s += v*v;
        }
        for (int o = 16; o; o >>= 1) s += __shfl_down_sync(0xffffffffu, s, o);
        if (lane == 0) dst[z*LTOK + t] = rsqrtf(s + 32.0f);
    }
}

// ---------------- transpose b per (bwn,h): [t][d] -> [d][t] ----------------
__global__ void k_tr_bv() {
    __shared__ float s[32][33];
    int z = blockIdx.z; int bwn = z >> 3, h = z & 7;
    int d0 = blockIdx.x * 32, t0 = blockIdx.y * 32;
    int tx = threadIdx.x, ty = threadIdx.y;
#pragma unroll
    for (int j = 0; j < 4; j++) {
        int t = t0 + ty*4 + j;
        s[ty*4+j][tx] = g_bv[((long)(bwn*LTOK + t))*EDIM + h*HDIM + d0 + tx];
    }
    __syncthreads();
#pragma unroll
    for (int j = 0; j < 4; j++) {
        int d = d0 + ty*4 + j;
        g_bvt[((long)(z*HDIM + d))*LTOK + t0 + tx] = s[tx][ty*4+j];
    }
}

// ---------------- transpose pos_embed: [c][pos] -> [pos][c] ----------------
__global__ void k_tr_pe(const float* __restrict__ pe) {
    __shared__ float s[32][33];
    int c0 = blockIdx.x * 32, p0 = blockIdx.y * 32;
    int tx = threadIdx.x, ty = threadIdx.y;
#pragma unroll
    for (int j = 0; j < 4; j++)
        s[ty*4+j][tx] = pe[(long)(c0 + ty*4 + j)*4096 + p0 + tx];
    __syncthreads();
#pragma unroll
    for (int j = 0; j < 4; j++)
        g_pet[(long)(p0 + ty*4 + j)*EDIM + c0 + tx] = s[tx][ty*4+j];
}

// ================= tf32 mma.sync GEMM (NT): C[M,N] = A[M,K] @ B[N,K]^T =================
// Tiles stored [m][k] with LDK=36 (bank-conflict-free fill AND fragment reads).
// 128 x (32*NMMA) CTA tile, BK=32, 8 warps (2x4), warp tile 64 x (8*NMMA).
// EPI 0: plain (+bias by col), batched
// EPI 1: conv-r: A gathered from g_rx (fused im2col), epilogue -> g_rp, z = b*3+g
// EPI 2: final projection -> out[b][oc][pos], bias by row
// EPI 3: av -> g_avt token-major scatter, NMMA=3, z = bwn*8+h
// EPI 4: attn: (S + G[dx]+G[dy]) * inq * inb, A/B per-head slices of g_q/g_bv
#define LDK  36
#define TB   (128*LDK)           // 4608 floats per tile buffer
#define SMEMSZ (4*TB*4 + 256)    // 73728 + 256 bytes

__device__ __forceinline__ uint32_t f2tf32(float f) {
    uint32_t u;
    asm("cvt.rna.tf32.f32 %0, %1;" : "=r"(u) : "f"(f));
    return u;
}
__device__ __forceinline__ float4 cvt4(float4 v) {
    v.x = __uint_as_float(f2tf32(v.x));
    v.y = __uint_as_float(f2tf32(v.y));
    v.z = __uint_as_float(f2tf32(v.z));
    v.w = __uint_as_float(f2tf32(v.w));
    return v;
}
__device__ __forceinline__ void mma8(float* d, const uint32_t* a, const uint32_t* b) {
    asm volatile(
        "mma.sync.aligned.m16n8k8.row.col.f32.tf32.tf32.f32 "
        "{%0,%1,%2,%3}, {%4,%5,%6,%7}, {%8,%9}, {%0,%1,%2,%3};"
        : "+f"(d[0]), "+f"(d[1]), "+f"(d[2]), "+f"(d[3])
        : "r"(a[0]), "r"(a[1]), "r"(a[2]), "r"(a[3]), "r"(b[0]), "r"(b[1]));
}

template<int EPI, int NMMA>
__global__ __launch_bounds__(256)
void tc_gemm(const float* __restrict__ A, const float* __restrict__ B,
             const float* __restrict__ bias, float* __restrict__ C,
             int K, int lda, int ldb, int ldc,
             long sA, long sB, long sC,
             const float* __restrict__ sr, const float* __restrict__ sc) {
    extern __shared__ __align__(16) float sm[];
    int tid = threadIdx.x;
    int wid = tid >> 5, lane = tid & 31;
    int tg = lane >> 2, t4 = lane & 3;
    long z = blockIdx.z;
    if (EPI == 4) {
        long off = (z >> 3) * (long)LTOK * EDIM + (z & 7) * HDIM;
        A += off; B += off;
        C += z * sC;
    } else {
        A += z * sA;
        if (EPI == 1) B += (z % 3) * 65536; else B += z * sB;
        if (EPI == 0) C += z * sC;
    }

    int row0 = blockIdx.y * 128, col0 = blockIdx.x * (32*NMMA);
    int wm = wid >> 2, wn = wid & 3;
    int m_base = wm * 64, n_base = wn * (8*NMMA);

    float acc[4][NMMA][4] = {};
    const int KT = K >> 5;

    // fill coords: m = i2>>3 (row), lc = (i2&7)*4 (k offset)
    int am[4], ac[4];
#pragma unroll
    for (int p = 0; p < 4; p++) {
        int i2 = tid + p*256;
        am[p] = i2 >> 3;
        ac[p] = (i2 & 7) << 2;
    }

    // A loader (handles fused-im2col for EPI 1)
    auto loadA = [&](int m, int k) -> float4 {
        if (EPI == 1) {
            int pos = row0 + m;
            int y = pos >> 6, xq = pos & 63;
            int py = k >> 4, px = k & 15;
            return *(const float4*)(g_rx + ((long)z*1024 + y*16 + py)*1024 + xq*16 + px);
        }
        return *(const float4*)(A + (long)(row0 + m)*lda + k);
    };

    float4 pa[4], pb[NMMA];
#pragma unroll
    for (int p = 0; p < 4; p++) pa[p] = loadA(am[p], ac[p]);
#pragma unroll
    for (int p = 0; p < NMMA; p++)
        pb[p] = *(const float4*)(B + (long)(col0 + am[p])*ldb + ac[p]);
#pragma unroll
    for (int p = 0; p < 4; p++)
        *(float4*)(sm + am[p]*LDK + ac[p]) = cvt4(pa[p]);
#pragma unroll
    for (int p = 0; p < NMMA; p++)
        *(float4*)(sm + 2*TB + am[p]*LDK + ac[p]) = cvt4(pb[p]);
    __syncthreads();

    for (int kt = 0; kt < KT; kt++) {
        int cur = kt & 1, nxt = cur ^ 1;
        if (kt + 1 < KT) {
            int k0 = (kt + 1) << 5;
#pragma unroll
            for (int p = 0; p < 4; p++) pa[p] = loadA(am[p], k0 + ac[p]);
#pragma unroll
            for (int p = 0; p < NMMA; p++)
                pb[p] = *(const float4*)(B + (long)(col0 + am[p])*ldb + k0 + ac[p]);
        }
        const float* As = sm + cur*TB;
        const float* Bs = sm + 2*TB + cur*TB;
#pragma unroll
        for (int ks = 0; ks < 4; ks++) {
            int kk = ks*8 + t4;
            const float* A0 = As + (m_base + tg)*LDK + kk;
            const float* B0 = Bs + (n_base + tg)*LDK + kk;
            uint32_t af[4][4], bf[NMMA][2];
#pragma unroll
            for (int im = 0; im < 4; im++) {
                af[im][0] = __float_as_uint(A0[im*16*LDK]);
                af[im][1] = __float_as_uint(A0[im*16*LDK + 8*LDK]);
                af[im][2] = __float_as_uint(A0[im*16*LDK + 4]);
                af[im][3] = __float_as_uint(A0[im*16*LDK + 8*LDK + 4]);
            }
#pragma unroll
            for (int in = 0; in < NMMA; in++) {
                bf[in][0] = __float_as_uint(B0[in*8*LDK]);
                bf[in][1] = __float_as_uint(B0[in*8*LDK + 4]);
            }
#pragma unroll
            for (int im = 0; im < 4; im++)
#pragma unroll
                for (int in = 0; in < NMMA; in++)
                    mma8(acc[im][in], af[im], bf[in]);
        }
        if (kt + 1 < KT) {
            __syncthreads();
#pragma unroll
            for (int p = 0; p < 4; p++)
                *(float4*)(sm + nxt*TB + am[p]*LDK + ac[p]) = cvt4(pa[p]);
#pragma unroll
            for (int p = 0; p < NMMA; p++)
                *(float4*)(sm + 2*TB + nxt*TB + am[p]*LDK + ac[p]) = cvt4(pb[p]);
            __syncthreads();
        }
    }

    // stage C through smem (first 16384 floats), xor-swizzled float4 slots
    __syncthreads();
    if (EPI == 4 && tid < 63) sm[4*TB + tid] = g_G[tid];
#pragma unroll
    for (int im = 0; im < 4; im++) {
#pragma unroll
        for (int in = 0; in < NMMA; in++) {
            int r = m_base + im*16 + tg;
            int c = n_base + in*8 + t4*2;
            int s0 = ((c >> 2) ^ (r & 31));
            float* p0 = sm + (r << 7) + (s0 << 2) + (c & 3);
            p0[0] = acc[im][in][0]; p0[1] = acc[im][in][1];
            int r2 = r + 8;
            int s2 = ((c >> 2) ^ (r2 & 31));
            float* p2 = sm + (r2 << 7) + (s2 << 2) + (c & 3);
            p2[0] = acc[im][in][2]; p2[1] = acc[im][in][3];
        }
    }
    __syncthreads();

#pragma unroll 1
    for (int pass = 0; pass < 16; pass++) {
        int r  = pass*8 + wid;
        int c4 = lane;
        if (NMMA == 3 && c4 >= 24) continue;
        int slot = c4 ^ (r & 31);
        float4 v = *(const float4*)(sm + (r << 7) + (slot << 2));
        int row = row0 + r;
        int col = col0 + (c4 << 2);
        if (EPI == 0) {
            if (bias) { v.x += bias[col]; v.y += bias[col+1]; v.z += bias[col+2]; v.w += bias[col+3]; }
            *(float4*)(C + (long)row*ldc + col) = v;
        } else if (EPI == 1) {
            int pos = row;
            int y = pos >> 6, xq = pos & 63;
            int bb_ = (int)(z / 3), g = (int)(z % 3);
            int bwn = (bb_*2 + (y>>5))*2 + (xq>>5);
            int t   = (y&31)*32 + (xq&31);
            int cc  = g*256 + col;
            float4 pb4 = *(const float4*)(g_pet + (long)pos*EDIM + cc);
            v.x += bias[cc+0] + pb4.x; v.y += bias[cc+1] + pb4.y;
            v.z += bias[cc+2] + pb4.z; v.w += bias[cc+3] + pb4.w;
            *(float4*)(g_rp + ((long)(bwn*LTOK + t))*EDIM + cc) = v;
        } else if (EPI == 2) {
            int oc = row, tok = col;
            int bb_ = tok >> 12, p = tok & 4095;
            float bia = bias[oc];
            v.x += bia; v.y += bia; v.z += bia; v.w += bia;
            *(float4*)(C + (long)bb_*(EDIM*4096) + (long)oc*4096 + p) = v;
        } else if (EPI == 3) {
            int bwn = (int)(z >> 3), h = (int)(z & 7);
            int t = row;
            int b_ = bwn >> 2, wy = (bwn >> 1) & 1, wx = bwn & 1;
            int ly = t >> 5, lx = t & 31;
            int tok = b_*4096 + (wy*32 + ly)*64 + (wx*32 + lx);
            *(float4*)(g_avt + (long)tok*EDIM + h*HDIM + (c4 << 2)) = v;
        } else { // EPI 4
            const float* smG = sm + 4*TB;
            int xi = row & 31, yi = row >> 5;
            float iq = sr[z*LTOK + row];
            float4 ib4 = *(const float4*)(sc + z*LTOK + col);
            int xj0 = col & 31, yj0 = col >> 5;
            v.x = (v.x + smG[xi - xj0     + 31] + smG[yi - yj0 + 31]) * iq * ib4.x;
            v.y = (v.y + smG[xi - (xj0+1) + 31] + smG[yi - yj0 + 31]) * iq * ib4.y;
            v.z = (v.z + smG[xi - (xj0+2) + 31] + smG[yi - yj0 + 31]) * iq * ib4.z;
            v.w = (v.w + smG[xi - (xj0+3) + 31] + smG[yi - yj0 + 31]) * iq * ib4.w;
            *(float4*)(C + (long)row*ldc + col) = v;
        }
    }
}

// ---------------- host launch ----------------
static float* sym_addr(const void* sym) {
    void* p = nullptr;
    cudaGetSymbolAddress(&p, sym);
    return (float*)p;
}

extern "C" void kernel_launch(void* const* d_in, const int* in_sizes, int n_in,
                              void* d_out, int out_size) {
    const float* x      = (const float*)d_in[0];
    const float* ow     = (const float*)d_in[1];
    const float* obias  = (const float*)d_in[2];
    const float* rw     = (const float*)d_in[3];
    const float* rbias  = (const float*)d_in[4];
    const float* pe     = (const float*)d_in[5];
    const float* nb_g   = (const float*)d_in[6];
    const float* nb_b   = (const float*)d_in[7];
    const float* nq_g   = (const float*)d_in[8];
    const float* nq_b   = (const float*)d_in[9];
    const float* qw     = (const float*)d_in[10];
    const float* qb     = (const float*)d_in[11];
    const float* bw     = (const float*)d_in[12];
    const float* bb     = (const float*)d_in[13];
    const float* projw  = (const float*)d_in[14];
    const float* projb  = (const float*)d_in[15];

    float* out  = (float*)d_out;
    float* attn = out + OUT_ELEMS;

    float* p_rx  = sym_addr(g_rx);
    float* p_rpn = sym_addr(g_rpn);
    float* p_opn = sym_addr(g_opn);
    float* p_q   = sym_addr(g_q);
    float* p_bv  = sym_addr(g_bv);
    float* p_avt = sym_addr(g_avt);
    float* p_bvt = sym_addr(g_bvt);
    float* p_inq = sym_addr(g_inq);
    float* p_inb = sym_addr(g_inb);

    cudaFuncSetAttribute(tc_gemm<0,4>, cudaFuncAttributeMaxDynamicSharedMemorySize, SMEMSZ);
    cudaFuncSetAttribute(tc_gemm<1,4>, cudaFuncAttributeMaxDynamicSharedMemorySize, SMEMSZ);
    cudaFuncSetAttribute(tc_gemm<2,4>, cudaFuncAttributeMaxDynamicSharedMemorySize, SMEMSZ);
    cudaFuncSetAttribute(tc_gemm<3,3>, cudaFuncAttributeMaxDynamicSharedMemorySize, SMEMSZ);
    cudaFuncSetAttribute(tc_gemm<4,4>, cudaFuncAttributeMaxDynamicSharedMemorySize, SMEMSZ);

    // order chosen so ncu (-s 5 -c 1) captures the q-projection GEMM (launch #6)
    k_tr_pe<<<dim3(24, 128), dim3(32, 8)>>>(pe);                       // 1
    k_resize<<<24576, 256>>>(x);                                       // 2
    k_conv_o<<<dim3(1024, BATCHN), 768>>>(x, ow, obias);               // 3
    // resize conv as tf32 GEMM with fused im2col gather (M=4096,N=256,K=256)
    tc_gemm<1,4><<<dim3(2, 32, 6), 256, SMEMSZ>>>(p_rx, rw, rbias, nullptr,
                                                  256, 256, 256, 0,
                                                  0, 0, 0, nullptr, nullptr);   // 4
    k_ln<<<dim3(BWIN*LTOK, 2), 256>>>(nb_g, nb_b, nq_g, nq_b);         // 5
    tc_gemm<0,4><<<dim3(6, 64, 1), 256, SMEMSZ>>>(p_rpn, qw, qb, p_q,
                                                  EDIM, EDIM, EDIM, EDIM, 0, 0, 0,
                                                  nullptr, nullptr);   // 6  <- profiled
    tc_gemm<0,4><<<dim3(6, 64, 1), 256, SMEMSZ>>>(p_opn, bw, bb, p_bv,
                                                  EDIM, EDIM, EDIM, EDIM, 0, 0, 0,
                                                  nullptr, nullptr);   // 7
    k_gtab<<<1, 64>>>();                                               // 8
    k_norm<<<dim3(BWIN*NHEADS, 2), 256>>>();                           // 9
    k_tr_bv<<<dim3(3, 32, 64), dim3(32, 8)>>>();                       // 10
    // attn = (q96·b96 + G) * inq * inb -> second output region
    tc_gemm<4,4><<<dim3(8, 8, BWIN*NHEADS), 256, SMEMSZ>>>(p_q, p_bv, nullptr, attn,
                                                           HDIM, EDIM, EDIM, LTOK,
                                                           0, 0, (long)LTOK*LTOK,
                                                           p_inq, p_inb);       // 11
    // av = attn @ b (N=96 exact) -> g_avt
    tc_gemm<3,3><<<dim3(1, 8, BWIN*NHEADS), 256, SMEMSZ>>>(attn, p_bvt, nullptr, nullptr,
                                                           LTOK, LTOK, LTOK, 0,
                                                           (long)LTOK*LTOK, (long)HDIM*LTOK, 0,
                                                           nullptr, nullptr);   // 12
    // final projection -> first output region
    tc_gemm<2,4><<<dim3(64, 6, 1), 256, SMEMSZ>>>(projw, p_avt, projb, out,
                                                  EDIM, EDIM, EDIM, 0, 0, 0, 0,
                                                  nullptr, nullptr);   // 13
}

// round 7
// speedup vs baseline: 9.3141x; 1.1701x over previous
#include <cuda_runtime.h>
#include <math.h>
#include <stdint.h>

// ---------------- problem constants ----------------
#define BATCHN  2
#define EDIM    768
#define LTOK    1024
#define BWIN    8
#define NHEADS  8
#define HDIM    96
#define OUT_ELEMS (BATCHN*EDIM*64*64)

// ---------------- scratch ----------------
__device__ float g_rx [BATCHN*3*1024*1024];
__device__ float g_op [BWIN*LTOK*EDIM];
__device__ float g_rp [BWIN*LTOK*EDIM];
__device__ float g_opn[BWIN*LTOK*EDIM];
__device__ float g_rpn[BWIN*LTOK*EDIM];
__device__ float g_q  [BWIN*LTOK*EDIM];
__device__ float g_bv [BWIN*LTOK*EDIM];
__device__ float g_avt[BATCHN*4096*EDIM];
__device__ float g_bvt[BWIN*NHEADS*HDIM*LTOK];
__device__ float g_pet[4096*EDIM];
__device__ float g_inq[BWIN*NHEADS*LTOK];
__device__ float g_inb[BWIN*NHEADS*LTOK];
__device__ float g_G  [64];
// tf32-pre-rounded weights
__device__ float g_wq[EDIM*EDIM];
__device__ float g_wb[EDIM*EDIM];
__device__ float g_wp[EDIM*EDIM];
__device__ float g_wr[768*256];

__device__ __forceinline__ uint32_t f2tf32(float f) {
    uint32_t u;
    asm("cvt.rna.tf32.f32 %0, %1;" : "=r"(u) : "f"(f));
    return u;
}
__device__ __forceinline__ float rtf(float f) { return __uint_as_float(f2tf32(f)); }
__device__ __forceinline__ float4 cvt4(float4 v) {
    v.x = rtf(v.x); v.y = rtf(v.y); v.z = rtf(v.z); v.w = rtf(v.w);
    return v;
}

// ---------------- weight pre-rounding ----------------
__global__ void k_cvtw(const float* __restrict__ qw, const float* __restrict__ bw,
                       const float* __restrict__ pw, const float* __restrict__ rw) {
    int i = blockIdx.x * blockDim.x + threadIdx.x;
    if (i < EDIM*EDIM) {
        g_wq[i] = rtf(qw[i]);
        g_wb[i] = rtf(bw[i]);
        g_wp[i] = rtf(pw[i]);
    }
    if (i < 768*256) g_wr[i] = rtf(rw[i]);
}

// ---------------- bilinear resize 512 -> 1024 (output pre-rounded: GEMM-A input) ----------------
__global__ void k_resize(const float* __restrict__ x) {
    int idx = blockIdx.x * blockDim.x + threadIdx.x;
    if (idx >= BATCHN*3*1024*1024) return;
    int ox = idx & 1023;
    int oy = (idx >> 10) & 1023;
    int ch = idx >> 20;
    float fy = oy * 0.5f - 0.25f;
    float fx = ox * 0.5f - 0.25f;
    int y0 = (int)floorf(fy); float ty = fy - (float)y0;
    int x0 = (int)floorf(fx); float tx = fx - (float)x0;
    int y1 = y0 + 1, x1 = x0 + 1;
    y0 = max(0, min(511, y0)); y1 = max(0, min(511, y1));
    x0 = max(0, min(511, x0)); x1 = max(0, min(511, x1));
    const float* p = x + (long)ch * 512 * 512;
    float v = p[y0*512+x0]*(1.f-ty)*(1.f-tx) + p[y0*512+x1]*(1.f-ty)*tx
            + p[y1*512+x0]*ty*(1.f-tx)       + p[y1*512+x1]*ty*tx;
    g_rx[idx] = rtf(v);
}

// ---------------- origin conv ----------------
__global__ void k_conv_o(const float* __restrict__ x, const float* __restrict__ w,
                         const float* __restrict__ bias) {
    __shared__ float patch[4*192];
    int b = blockIdx.y;
    int y  = blockIdx.x >> 4;
    int xg = blockIdx.x & 15;
    int tid = threadIdx.x;
    {
        int p = tid / 192, r = tid % 192;
        int c = r >> 6, pix = r & 63, py = pix >> 3, px = pix & 7;
        patch[tid] = x[(((long)(b*3+c))*512 + y*8+py)*512 + (xg*4+p)*8+px];
    }
    __syncthreads();
    int g = tid >> 8;
    const float* wp = w + (long)tid * 64;
    float s0 = 0.f, s1 = 0.f, s2 = 0.f, s3 = 0.f;
    const float* pp = patch + g * 64;
#pragma unroll
    for (int i = 0; i < 64; i++) {
        float wv = wp[i];
        s0 += wv * pp[i];
        s1 += wv * pp[i + 192];
        s2 += wv * pp[i + 384];
        s3 += wv * pp[i + 576];
    }
    float bia = bias[tid];
#pragma unroll
    for (int p = 0; p < 4; p++) {
        int xq = xg*4 + p;
        int bwn = (b*2 + (y>>5))*2 + (xq>>5);
        int t   = (y&31)*32 + (xq&31);
        float s = (p==0?s0:p==1?s1:p==2?s2:s3) + bia;
        g_op[((long)(bwn*LTOK + t))*EDIM + tid] = s;
    }
}

// ---------------- LayerNorm (output pre-rounded: GEMM-A input) ----------------
__global__ void k_ln(const float* __restrict__ g0, const float* __restrict__ b0,
                     const float* __restrict__ g1, const float* __restrict__ b1) {
    long row = blockIdx.x;
    const float* in = blockIdx.y ? g_rp : g_op;
    const float* gg = blockIdx.y ? g1 : g0;
    const float* bb = blockIdx.y ? b1 : b0;
    float* out = blockIdx.y ? g_rpn : g_opn;
    const float* r = in + row * EDIM;
    float v[3], s = 0.f, ss = 0.f;
#pragma unroll
    for (int j = 0; j < 3; j++) {
        float xv = r[threadIdx.x + j*256];
        v[j] = xv; s += xv; ss += xv*xv;
    }
    __shared__ float shs[8], shss[8];
    for (int o = 16; o; o >>= 1) {
        s  += __shfl_down_sync(0xffffffffu, s,  o);
        ss += __shfl_down_sync(0xffffffffu, ss, o);
    }
    if ((threadIdx.x & 31) == 0) { shs[threadIdx.x>>5] = s; shss[threadIdx.x>>5] = ss; }
    __syncthreads();
    if (threadIdx.x < 8) {
        s = shs[threadIdx.x]; ss = shss[threadIdx.x];
        for (int o = 4; o; o >>= 1) {
            s  += __shfl_down_sync(0xffu, s,  o);
            ss += __shfl_down_sync(0xffu, ss, o);
        }
        if (threadIdx.x == 0) { shs[0] = s; shss[0] = ss; }
    }
    __syncthreads();
    float mu  = shs[0] * (1.f/768.f);
    float var = shss[0] * (1.f/768.f) - mu*mu;
    float rin = rsqrtf(var + 1e-5f);
#pragma unroll
    for (int j = 0; j < 3; j++) {
        int c = threadIdx.x + j*256;
        out[row*EDIM + c] = rtf((v[j]-mu)*rin*gg[c] + bb[c]);
    }
}

// ---------------- RoPE delta table ----------------
__global__ void k_gtab() {
    int tid = threadIdx.x;
    if (tid < 63) {
        float d = (float)(tid - 31);
        float s = 0.f;
#pragma unroll
        for (int f = 0; f < 16; f++)
            s += cosf(d * powf(10.0f, -(float)f / 16.0f));
        g_G[tid] = s;
    }
}

// ---------------- per-row inverse norms ----------------
__global__ void k_norm() {
    int z = blockIdx.x;
    int bwn = z >> 3, h = z & 7;
    const float* src = blockIdx.y ? g_bv : g_q;
    float* dst       = blockIdx.y ? g_inb : g_inq;
    int wid = threadIdx.x >> 5, lane = threadIdx.x & 31;
    for (int t = wid; t < LTOK; t += 8) {
        const float* r = src + ((long)(bwn*LTOK + t))*EDIM + h*HDIM;
        float s = 0.f;
#pragma unroll
        for (int j = 0; j < 3; j++) {
            float v = r[lane + 32*j];
            s += v*v;
        }
        for (int o = 16; o; o >>= 1) s += __shfl_down_sync(0xffffffffu, s, o);
        if (lane == 0) dst[z*LTOK + t] = rsqrtf(s + 32.0f);
    }
}

// ---------------- transpose b per (bwn,h): [t][d] -> [d][t] (src already tf32) -------
__global__ void k_tr_bv() {
    __shared__ float s[32][33];
    int z = blockIdx.z; int bwn = z >> 3, h = z & 7;
    int d0 = blockIdx.x * 32, t0 = blockIdx.y * 32;
    int tx = threadIdx.x, ty = threadIdx.y;
#pragma unroll
    for (int j = 0; j < 4; j++) {
        int t = t0 + ty*4 + j;
        s[ty*4+j][tx] = g_bv[((long)(bwn*LTOK + t))*EDIM + h*HDIM + d0 + tx];
    }
    __syncthreads();
#pragma unroll
    for (int j = 0; j < 4; j++) {
        int d = d0 + ty*4 + j;
        g_bvt[((long)(z*HDIM + d))*LTOK + t0 + tx] = s[tx][ty*4+j];
    }
}

// ---------------- transpose pos_embed: [c][pos] -> [pos][c] ----------------
__global__ void k_tr_pe(const float* __restrict__ pe) {
    __shared__ float s[32][33];
    int c0 = blockIdx.x * 32, p0 = blockIdx.y * 32;
    int tx = threadIdx.x, ty = threadIdx.y;
#pragma unroll
    for (int j = 0; j < 4; j++)
        s[ty*4+j][tx] = pe[(long)(c0 + ty*4 + j)*4096 + p0 + tx];
    __syncthreads();
#pragma unroll
    for (int j = 0; j < 4; j++)
        g_pet[(long)(p0 + ty*4 + j)*EDIM + c0 + tx] = s[tx][ty*4+j];
}

// ================= tf32 mma.sync GEMM (NT) with 3-stage cp.async pipeline =================
// All mma inputs are pre-rounded to tf32 -> raw smem feeds mma directly (no cvt in loop).
// Tiles [m][k], LDK=36 (conflict-free fragment reads). One __syncthreads per k-chunk.
// EPI 0: plain (+bias), output pre-rounded (g_q/g_bv feed attn GEMM)
// EPI 1: conv-r, A gathered from g_rx (fused im2col), -> g_rp
// EPI 2: final projection -> out (full fp32)
// EPI 3: av -> g_avt (pre-rounded, feeds final proj)
// EPI 4: attn epilogue (pre-rounded, is output AND feeds AV)
#define LDK    36
#define TB     (128*LDK)             // 4608 floats per tile
#define STAGES 3
#define SMEMSZ ((2*STAGES*TB + 64)*4)  // 110848 bytes

__device__ __forceinline__ void cpa16(uint32_t d, const void* s) {
    asm volatile("cp.async.cg.shared.global [%0], [%1], 16;" :: "r"(d), "l"(s));
}
#define CP_COMMIT() asm volatile("cp.async.commit_group;" ::: "memory")
#define CP_WAIT1()  asm volatile("cp.async.wait_group 1;" ::: "memory")

__device__ __forceinline__ void mma8(float* d, const uint32_t* a, const uint32_t* b) {
    asm volatile(
        "mma.sync.aligned.m16n8k8.row.col.f32.tf32.tf32.f32 "
        "{%0,%1,%2,%3}, {%4,%5,%6,%7}, {%8,%9}, {%0,%1,%2,%3};"
        : "+f"(d[0]), "+f"(d[1]), "+f"(d[2]), "+f"(d[3])
        : "r"(a[0]), "r"(a[1]), "r"(a[2]), "r"(a[3]), "r"(b[0]), "r"(b[1]));
}

template<int EPI, int NMMA>
__global__ __launch_bounds__(256)
void tc_gemm(const float* __restrict__ A, const float* __restrict__ B,
             const float* __restrict__ bias, float* __restrict__ C,
             int K, int lda, int ldb, int ldc,
             long sA, long sB, long sC,
             const float* __restrict__ sr, const float* __restrict__ sc) {
    extern __shared__ __align__(16) float sm[];
    uint32_t sbase = (uint32_t)__cvta_generic_to_shared(sm);
    int tid = threadIdx.x;
    int wid = tid >> 5, lane = tid & 31;
    int tg = lane >> 2, t4 = lane & 3;
    long z = blockIdx.z;
    if (EPI == 4) {
        long off = (z >> 3) * (long)LTOK * EDIM + (z & 7) * HDIM;
        A += off; B += off;
        C += z * sC;
    } else {
        A += z * sA;
        if (EPI == 1) B += (z % 3) * 65536; else B += z * sB;
        if (EPI == 0) C += z * sC;
    }

    int row0 = blockIdx.y * 128, col0 = blockIdx.x * (32*NMMA);
    int wm = wid >> 2, wn = wid & 3;
    int m_base = wm * 64, n_base = wn * (8*NMMA);

    float acc[4][NMMA][4] = {};
    const int KT = K >> 5;

    int am[4], ac[4];
#pragma unroll
    for (int p = 0; p < 4; p++) {
        int i2 = tid + p*256;
        am[p] = i2 >> 3;
        ac[p] = (i2 & 7) << 2;
    }

    auto fill = [&](int kt) {
        int stg = kt % STAGES;
        int k0 = kt << 5;
        uint32_t ab = sbase + (uint32_t)(stg * (2*TB)) * 4u;
        uint32_t bb = ab + TB*4u;
#pragma unroll
        for (int p = 0; p < 4; p++) {
            const float* srcA;
            if (EPI == 1) {
                int pos = row0 + am[p];
                int y = pos >> 6, xq = pos & 63;
                int k = k0 + ac[p];
                int py = k >> 4, px = k & 15;
                srcA = g_rx + ((long)z*1024 + y*16 + py)*1024 + xq*16 + px;
            } else {
                srcA = A + (long)(row0 + am[p])*lda + k0 + ac[p];
            }
            cpa16(ab + (uint32_t)(am[p]*LDK + ac[p])*4u, srcA);
        }
#pragma unroll
        for (int p = 0; p < NMMA; p++)
            cpa16(bb + (uint32_t)(am[p]*LDK + ac[p])*4u,
                  B + (long)(col0 + am[p])*ldb + k0 + ac[p]);
    };

    fill(0); CP_COMMIT();
    fill(1); CP_COMMIT();

    for (int kt = 0; kt < KT; kt++) {
        CP_WAIT1();
        __syncthreads();
        if (kt + 2 < KT) fill(kt + 2);
        CP_COMMIT();                       // empty groups keep wait_group(1) exact at tail
        const float* As = sm + (kt % STAGES) * (2*TB);
        const float* Bs = As + TB;
#pragma unroll
        for (int ks = 0; ks < 4; ks++) {
            int kk = ks*8 + t4;
            const float* A0 = As + (m_base + tg)*LDK + kk;
            const float* B0 = Bs + (n_base + tg)*LDK + kk;
            uint32_t af[4][4], bf[NMMA][2];
#pragma unroll
            for (int im = 0; im < 4; im++) {
                af[im][0] = __float_as_uint(A0[im*16*LDK]);
                af[im][1] = __float_as_uint(A0[im*16*LDK + 8*LDK]);
                af[im][2] = __float_as_uint(A0[im*16*LDK + 4]);
                af[im][3] = __float_as_uint(A0[im*16*LDK + 8*LDK + 4]);
            }
#pragma unroll
            for (int in = 0; in < NMMA; in++) {
                bf[in][0] = __float_as_uint(B0[in*8*LDK]);
                bf[in][1] = __float_as_uint(B0[in*8*LDK + 4]);
            }
#pragma unroll
            for (int im = 0; im < 4; im++)
#pragma unroll
                for (int in = 0; in < NMMA; in++)
                    mma8(acc[im][in], af[im], bf[in]);
        }
    }

    // stage C through smem (first 16384 floats), xor-swizzled float4 slots
    __syncthreads();
    if (EPI == 4 && tid < 63) sm[2*STAGES*TB + tid] = g_G[tid];
#pragma unroll
    for (int im = 0; im < 4; im++) {
#pragma unroll
        for (int in = 0; in < NMMA; in++) {
            int r = m_base + im*16 + tg;
            int c = n_base + in*8 + t4*2;
            int s0 = ((c >> 2) ^ (r & 31));
            float* p0 = sm + (r << 7) + (s0 << 2) + (c & 3);
            p0[0] = acc[im][in][0]; p0[1] = acc[im][in][1];
            int r2 = r + 8;
            int s2 = ((c >> 2) ^ (r2 & 31));
            float* p2 = sm + (r2 << 7) + (s2 << 2) + (c & 3);
            p2[0] = acc[im][in][2]; p2[1] = acc[im][in][3];
        }
    }
    __syncthreads();

#pragma unroll 1
    for (int pass = 0; pass < 16; pass++) {
        int r  = pass*8 + wid;
        int c4 = lane;
        if (NMMA == 3 && c4 >= 24) continue;
        int slot = c4 ^ (r & 31);
        float4 v = *(const float4*)(sm + (r << 7) + (slot << 2));
        int row = row0 + r;
        int col = col0 + (c4 << 2);
        if (EPI == 0) {
            if (bias) { v.x += bias[col]; v.y += bias[col+1]; v.z += bias[col+2]; v.w += bias[col+3]; }
            *(float4*)(C + (long)row*ldc + col) = cvt4(v);
        } else if (EPI == 1) {
            int pos = row;
            int y = pos >> 6, xq = pos & 63;
            int bb_ = (int)(z / 3), g = (int)(z % 3);
            int bwn = (bb_*2 + (y>>5))*2 + (xq>>5);
            int t   = (y&31)*32 + (xq&31);
            int cc  = g*256 + col;
            float4 pb4 = *(const float4*)(g_pet + (long)pos*EDIM + cc);
            v.x += bias[cc+0] + pb4.x; v.y += bias[cc+1] + pb4.y;
            v.z += bias[cc+2] + pb4.z; v.w += bias[cc+3] + pb4.w;
            *(float4*)(g_rp + ((long)(bwn*LTOK + t))*EDIM + cc) = v;
        } else if (EPI == 2) {
            int oc = row, tok = col;
            int bb_ = tok >> 12, p = tok & 4095;
            float bia = bias[oc];
            v.x += bia; v.y += bia; v.z += bia; v.w += bia;
            *(float4*)(C + (long)bb_*(EDIM*4096) + (long)oc*4096 + p) = v;
        } else if (EPI == 3) {
            int bwn = (int)(z >> 3), h = (int)(z & 7);
            int t = row;
            int b_ = bwn >> 2, wy = (bwn >> 1) & 1, wx = bwn & 1;
            int ly = t >> 5, lx = t & 31;
            int tok = b_*4096 + (wy*32 + ly)*64 + (wx*32 + lx);
            *(float4*)(g_avt + (long)tok*EDIM + h*HDIM + (c4 << 2)) = cvt4(v);
        } else { // EPI 4
            const float* smG = sm + 2*STAGES*TB;
            int xi = row & 31, yi = row >> 5;
            float iq = sr[z*LTOK + row];
            float4 ib4 = *(const float4*)(sc + z*LTOK + col);
            int xj0 = col & 31, yj0 = col >> 5;
            v.x = (v.x + smG[xi - xj0     + 31] + smG[yi - yj0 + 31]) * iq * ib4.x;
            v.y = (v.y + smG[xi - (xj0+1) + 31] + smG[yi - yj0 + 31]) * iq * ib4.y;
            v.z = (v.z + smG[xi - (xj0+2) + 31] + smG[yi - yj0 + 31]) * iq * ib4.z;
            v.w = (v.w + smG[xi - (xj0+3) + 31] + smG[yi - yj0 + 31]) * iq * ib4.w;
            *(float4*)(C + (long)row*ldc + col) = cvt4(v);
        }
    }
}

// ---------------- host launch ----------------
static float* sym_addr(const void* sym) {
    void* p = nullptr;
    cudaGetSymbolAddress(&p, sym);
    return (float*)p;
}

extern "C" void kernel_launch(void* const* d_in, const int* in_sizes, int n_in,
                              void* d_out, int out_size) {
    const float* x      = (const float*)d_in[0];
    const float* ow     = (const float*)d_in[1];
    const float* obias  = (const float*)d_in[2];
    const float* rw     = (const float*)d_in[3];
    const float* rbias  = (const float*)d_in[4];
    const float* pe     = (const float*)d_in[5];
    const float* nb_g   = (const float*)d_in[6];
    const float* nb_b   = (const float*)d_in[7];
    const float* nq_g   = (const float*)d_in[8];
    const float* nq_b   = (const float*)d_in[9];
    const float* qw     = (const float*)d_in[10];
    const float* qb     = (const float*)d_in[11];
    const float* bw     = (const float*)d_in[12];
    const float* bb     = (const float*)d_in[13];
    const float* projw  = (const float*)d_in[14];
    const float* projb  = (const float*)d_in[15];

    float* out  = (float*)d_out;
    float* attn = out + OUT_ELEMS;

    float* p_rx  = sym_addr(g_rx);
    float* p_rpn = sym_addr(g_rpn);
    float* p_opn = sym_addr(g_opn);
    float* p_q   = sym_addr(g_q);
    float* p_bv  = sym_addr(g_bv);
    float* p_avt = sym_addr(g_avt);
    float* p_bvt = sym_addr(g_bvt);
    float* p_inq = sym_addr(g_inq);
    float* p_inb = sym_addr(g_inb);
    float* p_wq  = sym_addr(g_wq);
    float* p_wb  = sym_addr(g_wb);
    float* p_wp  = sym_addr(g_wp);
    float* p_wr  = sym_addr(g_wr);

    cudaFuncSetAttribute(tc_gemm<0,4>, cudaFuncAttributeMaxDynamicSharedMemorySize, SMEMSZ);
    cudaFuncSetAttribute(tc_gemm<1,4>, cudaFuncAttributeMaxDynamicSharedMemorySize, SMEMSZ);
    cudaFuncSetAttribute(tc_gemm<2,4>, cudaFuncAttributeMaxDynamicSharedMemorySize, SMEMSZ);
    cudaFuncSetAttribute(tc_gemm<3,3>, cudaFuncAttributeMaxDynamicSharedMemorySize, SMEMSZ);
    cudaFuncSetAttribute(tc_gemm<4,4>, cudaFuncAttributeMaxDynamicSharedMemorySize, SMEMSZ);

    k_cvtw<<<2304, 256>>>(qw, bw, projw, rw);                          // 1
    k_tr_pe<<<dim3(24, 128), dim3(32, 8)>>>(pe);                       // 2
    k_resize<<<24576, 256>>>(x);                                       // 3
    k_conv_o<<<dim3(1024, BATCHN), 768>>>(x, ow, obias);               // 4
    // resize conv as tf32 GEMM with fused im2col gather (M=4096,N=256,K=256)
    tc_gemm<1,4><<<dim3(2, 32, 6), 256, SMEMSZ>>>(p_rx, p_wr, rbias, nullptr,
                                                  256, 256, 256, 0,
                                                  0, 0, 0, nullptr, nullptr);   // 5
    k_ln<<<dim3(BWIN*LTOK, 2), 256>>>(nb_g, nb_b, nq_g, nq_b);         // 6 <- profiled slot
    tc_gemm<0,4><<<dim3(6, 64, 1), 256, SMEMSZ>>>(p_rpn, p_wq, qb, p_q,
                                                  EDIM, EDIM, EDIM, EDIM, 0, 0, 0,
                                                  nullptr, nullptr);   // 7
    tc_gemm<0,4><<<dim3(6, 64, 1), 256, SMEMSZ>>>(p_opn, p_wb, bb, p_bv,
                                                  EDIM, EDIM, EDIM, EDIM, 0, 0, 0,
                                                  nullptr, nullptr);   // 8
    k_gtab<<<1, 64>>>();                                               // 9
    k_norm<<<dim3(BWIN*NHEADS, 2), 256>>>();                           // 10
    k_tr_bv<<<dim3(3, 32, 64), dim3(32, 8)>>>();                       // 11
    // attn = (q96·b96 + G) * inq * inb -> second output region
    tc_gemm<4,4><<<dim3(8, 8, BWIN*NHEADS), 256, SMEMSZ>>>(p_q, p_bv, nullptr, attn,
                                                           HDIM, EDIM, EDIM, LTOK,
                                                           0, 0, (long)LTOK*LTOK,
                                                           p_inq, p_inb);       // 12
    // av = attn @ b (N=96 exact) -> g_avt
    tc_gemm<3,3><<<dim3(1, 8, BWIN*NHEADS), 256, SMEMSZ>>>(attn, p_bvt, nullptr, nullptr,
                                                           LTOK, LTOK, LTOK, 0,
                                                           (long)LTOK*LTOK, (long)HDIM*LTOK, 0,
                                                           nullptr, nullptr);   // 13
    // final projection -> first output region
    tc_gemm<2,4><<<dim3(64, 6, 1), 256, SMEMSZ>>>(p_wp, p_avt, projb, out,
                                                  EDIM, EDIM, EDIM, 0, 0, 0, 0,
                                                  nullptr, nullptr);   // 14
}

// round 8
// speedup vs baseline: 13.5777x; 1.4578x over previous
#include <cuda_runtime.h>
#include <math.h>
#include <stdint.h>

// ---------------- problem constants ----------------
#define BATCHN  2
#define EDIM    768
#define LTOK    1024
#define BWIN    8
#define NHEADS  8
#define HDIM    96
#define OUT_ELEMS (BATCHN*EDIM*64*64)

// ---------------- scratch ----------------
__device__ float g_rx [BATCHN*3*1024*1024];
__device__ float g_op [BWIN*LTOK*EDIM];
__device__ float g_rp [BWIN*LTOK*EDIM];
__device__ float g_opn[BWIN*LTOK*EDIM];
__device__ float g_rpn[BWIN*LTOK*EDIM];
__device__ float g_q  [BWIN*LTOK*EDIM];
__device__ float g_bv [BWIN*LTOK*EDIM];
__device__ float g_avt[BATCHN*4096*EDIM];
__device__ float g_bvt[BWIN*NHEADS*HDIM*LTOK];
__device__ float g_pet[4096*EDIM];
__device__ float g_inq[BWIN*NHEADS*LTOK];
__device__ float g_inb[BWIN*NHEADS*LTOK];
__device__ float g_G  [64];
// tf32-pre-rounded weights
__device__ float g_wq[EDIM*EDIM];
__device__ float g_wb[EDIM*EDIM];
__device__ float g_wp[EDIM*EDIM];
__device__ float g_wr[768*256];
__device__ float g_wo[64*768];     // origin conv weights transposed [i][oc], fp32

__device__ __forceinline__ uint32_t f2tf32(float f) {
    uint32_t u;
    asm("cvt.rna.tf32.f32 %0, %1;" : "=r"(u) : "f"(f));
    return u;
}
__device__ __forceinline__ float rtf(float f) { return __uint_as_float(f2tf32(f)); }
__device__ __forceinline__ float4 cvt4(float4 v) {
    v.x = rtf(v.x); v.y = rtf(v.y); v.z = rtf(v.z); v.w = rtf(v.w);
    return v;
}

// ---------------- weight pre-rounding + origin-weight transpose ----------------
__global__ void k_cvtw(const float* __restrict__ qw, const float* __restrict__ bw,
                       const float* __restrict__ pw, const float* __restrict__ rw,
                       const float* __restrict__ ow) {
    int i = blockIdx.x * blockDim.x + threadIdx.x;
    if (i < EDIM*EDIM) {
        g_wq[i] = rtf(qw[i]);
        g_wb[i] = rtf(bw[i]);
        g_wp[i] = rtf(pw[i]);
    }
    if (i < 768*256) g_wr[i] = rtf(rw[i]);
    if (i < 64*768) {
        int ki = i / 768, oc = i % 768;      // dst [ki][oc]
        g_wo[i] = ow[oc*64 + ki];            // src [oc][ki], fp32 exact
    }
}

// ---------------- bilinear resize 512 -> 1024 (output pre-rounded: GEMM-A input) ----------------
__global__ void k_resize(const float* __restrict__ x) {
    int idx = blockIdx.x * blockDim.x + threadIdx.x;
    if (idx >= BATCHN*3*1024*1024) return;
    int ox = idx & 1023;
    int oy = (idx >> 10) & 1023;
    int ch = idx >> 20;
    float fy = oy * 0.5f - 0.25f;
    float fx = ox * 0.5f - 0.25f;
    int y0 = (int)floorf(fy); float ty = fy - (float)y0;
    int x0 = (int)floorf(fx); float tx = fx - (float)x0;
    int y1 = y0 + 1, x1 = x0 + 1;
    y0 = max(0, min(511, y0)); y1 = max(0, min(511, y1));
    x0 = max(0, min(511, x0)); x1 = max(0, min(511, x1));
    const float* p = x + (long)ch * 512 * 512;
    float v = p[y0*512+x0]*(1.f-ty)*(1.f-tx) + p[y0*512+x1]*(1.f-ty)*tx
            + p[y1*512+x0]*ty*(1.f-tx)       + p[y1*512+x1]*ty*tx;
    g_rx[idx] = rtf(v);
}

// ---------------- origin conv: coalesced transposed weights, 16 positions/block ----------------
__global__ void k_conv_o(const float* __restrict__ x, const float* __restrict__ bias) {
    __shared__ float patch[16*192];                 // 12 KB
    int b  = blockIdx.y;
    int y  = blockIdx.x >> 2;                       // 0..63
    int xg = blockIdx.x & 3;                        // group of 16 x positions
    int tid = threadIdx.x;                          // 768 = out channels
    for (int e = tid; e < 16*192; e += 768) {
        int p = e / 192, r = e % 192;
        int c = r >> 6, pix = r & 63, py = pix >> 3, px = pix & 7;
        patch[e] = x[(((long)(b*3+c))*512 + y*8+py)*512 + (xg*16+p)*8+px];
    }
    __syncthreads();
    int g = tid >> 8;
    float acc[16];
    float bia = bias[tid];
#pragma unroll
    for (int p = 0; p < 16; p++) acc[p] = bia;
    const float* wt = g_wo + tid;
    const float* pg = patch + g*64;
#pragma unroll 8
    for (int i = 0; i < 64; i++) {
        float wv = wt[i*768];                       // coalesced across warp
#pragma unroll
        for (int p = 0; p < 16; p++)
            acc[p] += wv * pg[p*192 + i];           // smem broadcast
    }
#pragma unroll
    for (int p = 0; p < 16; p++) {
        int xq = xg*16 + p;
        int bwn = (b*2 + (y>>5))*2 + (xq>>5);
        int t   = (y&31)*32 + (xq&31);
        g_op[((long)(bwn*LTOK + t))*EDIM + tid] = acc[p];
    }
}

// ---------------- LayerNorm (output pre-rounded: GEMM-A input) ----------------
__global__ void k_ln(const float* __restrict__ g0, const float* __restrict__ b0,
                     const float* __restrict__ g1, const float* __restrict__ b1) {
    long row = blockIdx.x;
    const float* in = blockIdx.y ? g_rp : g_op;
    const float* gg = blockIdx.y ? g1 : g0;
    const float* bb = blockIdx.y ? b1 : b0;
    float* out = blockIdx.y ? g_rpn : g_opn;
    const float* r = in + row * EDIM;
    float v[3], s = 0.f, ss = 0.f;
#pragma unroll
    for (int j = 0; j < 3; j++) {
        float xv = r[threadIdx.x + j*256];
        v[j] = xv; s += xv; ss += xv*xv;
    }
    __shared__ float shs[8], shss[8];
    for (int o = 16; o; o >>= 1) {
        s  += __shfl_down_sync(0xffffffffu, s,  o);
        ss += __shfl_down_sync(0xffffffffu, ss, o);
    }
    if ((threadIdx.x & 31) == 0) { shs[threadIdx.x>>5] = s; shss[threadIdx.x>>5] = ss; }
    __syncthreads();
    if (threadIdx.x < 8) {
        s = shs[threadIdx.x]; ss = shss[threadIdx.x];
        for (int o = 4; o; o >>= 1) {
            s  += __shfl_down_sync(0xffu, s,  o);
            ss += __shfl_down_sync(0xffu, ss, o);
        }
        if (threadIdx.x == 0) { shs[0] = s; shss[0] = ss; }
    }
    __syncthreads();
    float mu  = shs[0] * (1.f/768.f);
    float var = shss[0] * (1.f/768.f) - mu*mu;
    float rin = rsqrtf(var + 1e-5f);
#pragma unroll
    for (int j = 0; j < 3; j++) {
        int c = threadIdx.x + j*256;
        out[row*EDIM + c] = rtf((v[j]-mu)*rin*gg[c] + bb[c]);
    }
}

// ---------------- RoPE delta table ----------------
__global__ void k_gtab() {
    int tid = threadIdx.x;
    if (tid < 63) {
        float d = (float)(tid - 31);
        float s = 0.f;
#pragma unroll
        for (int f = 0; f < 16; f++)
            s += cosf(d * powf(10.0f, -(float)f / 16.0f));
        g_G[tid] = s;
    }
}

// ---------------- per-row inverse norms ----------------
__global__ void k_norm() {
    int z = blockIdx.x;
    int bwn = z >> 3, h = z & 7;
    const float* src = blockIdx.y ? g_bv : g_q;
    float* dst       = blockIdx.y ? g_inb : g_inq;
    int wid = threadIdx.x >> 5, lane = threadIdx.x & 31;
    for (int t = wid; t < LTOK; t += 8) {
        const float* r = src + ((long)(bwn*LTOK + t))*EDIM + h*HDIM;
        float s = 0.f;
#pragma unroll
        for (int j = 0; j < 3; j++) {
            float v = r[lane + 32*j];
            s += v*v;
        }
        for (int o = 16; o; o >>= 1) s += __shfl_down_sync(0xffffffffu, s, o);
        if (lane == 0) dst[z*LTOK + t] = rsqrtf(s + 32.0f);
    }
}

// ---------------- transpose b per (bwn,h): [t][d] -> [d][t] ----------------
__global__ void k_tr_bv() {
    __shared__ float s[32][33];
    int z = blockIdx.z; int bwn = z >> 3, h = z & 7;
    int d0 = blockIdx.x * 32, t0 = blockIdx.y * 32;
    int tx = threadIdx.x, ty = threadIdx.y;
#pragma unroll
    for (int j = 0; j < 4; j++) {
        int t = t0 + ty*4 + j;
        s[ty*4+j][tx] = g_bv[((long)(bwn*LTOK + t))*EDIM + h*HDIM + d0 + tx];
    }
    __syncthreads();
#pragma unroll
    for (int j = 0; j < 4; j++) {
        int d = d0 + ty*4 + j;
        g_bvt[((long)(z*HDIM + d))*LTOK + t0 + tx] = s[tx][ty*4+j];
    }
}

// ---------------- transpose pos_embed: [c][pos] -> [pos][c] ----------------
__global__ void k_tr_pe(const float* __restrict__ pe) {
    __shared__ float s[32][33];
    int c0 = blockIdx.x * 32, p0 = blockIdx.y * 32;
    int tx = threadIdx.x, ty = threadIdx.y;
#pragma unroll
    for (int j = 0; j < 4; j++)
        s[ty*4+j][tx] = pe[(long)(c0 + ty*4 + j)*4096 + p0 + tx];
    __syncthreads();
#pragma unroll
    for (int j = 0; j < 4; j++)
        g_pet[(long)(p0 + ty*4 + j)*EDIM + c0 + tx] = s[tx][ty*4+j];
}

// ================= tf32 mma.sync GEMM (NT) with 3-stage cp.async pipeline =================
#define LDK    36
#define TB     (128*LDK)
#define STAGES 3
#define SMEMSZ ((2*STAGES*TB + 64)*4)

__device__ __forceinline__ void cpa16(uint32_t d, const void* s) {
    asm volatile("cp.async.cg.shared.global [%0], [%1], 16;" :: "r"(d), "l"(s));
}
#define CP_COMMIT() asm volatile("cp.async.commit_group;" ::: "memory")
#define CP_WAIT1()  asm volatile("cp.async.wait_group 1;" ::: "memory")

__device__ __forceinline__ void mma8(float* d, const uint32_t* a, const uint32_t* b) {
    asm volatile(
        "mma.sync.aligned.m16n8k8.row.col.f32.tf32.tf32.f32 "
        "{%0,%1,%2,%3}, {%4,%5,%6,%7}, {%8,%9}, {%0,%1,%2,%3};"
        : "+f"(d[0]), "+f"(d[1]), "+f"(d[2]), "+f"(d[3])
        : "r"(a[0]), "r"(a[1]), "r"(a[2]), "r"(a[3]), "r"(b[0]), "r"(b[1]));
}

template<int EPI, int NMMA>
__global__ __launch_bounds__(256)
void tc_gemm(const float* __restrict__ A, const float* __restrict__ B,
             const float* __restrict__ bias, float* __restrict__ C,
             int K, int lda, int ldb, int ldc,
             long sA, long sB, long sC,
             const float* __restrict__ sr, const float* __restrict__ sc) {
    extern __shared__ __align__(16) float sm[];
    uint32_t sbase = (uint32_t)__cvta_generic_to_shared(sm);
    int tid = threadIdx.x;
    int wid = tid >> 5, lane = tid & 31;
    int tg = lane >> 2, t4 = lane & 3;
    long z = blockIdx.z;
    if (EPI == 4) {
        long off = (z >> 3) * (long)LTOK * EDIM + (z & 7) * HDIM;
        A += off; B += off;
        C += z * sC;
    } else {
        A += z * sA;
        if (EPI == 1) B += (z % 3) * 65536; else B += z * sB;
        if (EPI == 0) C += z * sC;
    }

    int row0 = blockIdx.y * 128, col0 = blockIdx.x * (32*NMMA);
    int wm = wid >> 2, wn = wid & 3;
    int m_base = wm * 64, n_base = wn * (8*NMMA);

    float acc[4][NMMA][4] = {};
    const int KT = K >> 5;

    int am[4], ac[4];
#pragma unroll
    for (int p = 0; p < 4; p++) {
        int i2 = tid + p*256;
        am[p] = i2 >> 3;
        ac[p] = (i2 & 7) << 2;
    }

    auto fill = [&](int kt) {
        int stg = kt % STAGES;
        int k0 = kt << 5;
        uint32_t ab = sbase + (uint32_t)(stg * (2*TB)) * 4u;
        uint32_t bb = ab + TB*4u;
#pragma unroll
        for (int p = 0; p < 4; p++) {
            const float* srcA;
            if (EPI == 1) {
                int pos = row0 + am[p];
                int y = pos >> 6, xq = pos & 63;
                int k = k0 + ac[p];
                int py = k >> 4, px = k & 15;
                srcA = g_rx + ((long)z*1024 + y*16 + py)*1024 + xq*16 + px;
            } else {
                srcA = A + (long)(row0 + am[p])*lda + k0 + ac[p];
            }
            cpa16(ab + (uint32_t)(am[p]*LDK + ac[p])*4u, srcA);
        }
#pragma unroll
        for (int p = 0; p < NMMA; p++)
            cpa16(bb + (uint32_t)(am[p]*LDK + ac[p])*4u,
                  B + (long)(col0 + am[p])*ldb + k0 + ac[p]);
    };

    fill(0); CP_COMMIT();
    fill(1); CP_COMMIT();

    for (int kt = 0; kt < KT; kt++) {
        CP_WAIT1();
        __syncthreads();
        if (kt + 2 < KT) fill(kt + 2);
        CP_COMMIT();
        const float* As = sm + (kt % STAGES) * (2*TB);
        const float* Bs = As + TB;
#pragma unroll
        for (int ks = 0; ks < 4; ks++) {
            int kk = ks*8 + t4;
            const float* A0 = As + (m_base + tg)*LDK + kk;
            const float* B0 = Bs + (n_base + tg)*LDK + kk;
            uint32_t af[4][4], bf[NMMA][2];
#pragma unroll
            for (int im = 0; im < 4; im++) {
                af[im][0] = __float_as_uint(A0[im*16*LDK]);
                af[im][1] = __float_as_uint(A0[im*16*LDK + 8*LDK]);
                af[im][2] = __float_as_uint(A0[im*16*LDK + 4]);
                af[im][3] = __float_as_uint(A0[im*16*LDK + 8*LDK + 4]);
            }
#pragma unroll
            for (int in = 0; in < NMMA; in++) {
                bf[in][0] = __float_as_uint(B0[in*8*LDK]);
                bf[in][1] = __float_as_uint(B0[in*8*LDK + 4]);
            }
#pragma unroll
            for (int im = 0; im < 4; im++)
#pragma unroll
                for (int in = 0; in < NMMA; in++)
                    mma8(acc[im][in], af[im], bf[in]);
        }
    }

    __syncthreads();
    if (EPI == 4 && tid < 63) sm[2*STAGES*TB + tid] = g_G[tid];
#pragma unroll
    for (int im = 0; im < 4; im++) {
#pragma unroll
        for (int in = 0; in < NMMA; in++) {
            int r = m_base + im*16 + tg;
            int c = n_base + in*8 + t4*2;
            int s0 = ((c >> 2) ^ (r & 31));
            float* p0 = sm + (r << 7) + (s0 << 2) + (c & 3);
            p0[0] = acc[im][in][0]; p0[1] = acc[im][in][1];
            int r2 = r + 8;
            int s2 = ((c >> 2) ^ (r2 & 31));
            float* p2 = sm + (r2 << 7) + (s2 << 2) + (c & 3);
            p2[0] = acc[im][in][2]; p2[1] = acc[im][in][3];
        }
    }
    __syncthreads();

#pragma unroll 1
    for (int pass = 0; pass < 16; pass++) {
        int r  = pass*8 + wid;
        int c4 = lane;
        if (NMMA == 3 && c4 >= 24) continue;
        int slot = c4 ^ (r & 31);
        float4 v = *(const float4*)(sm + (r << 7) + (slot << 2));
        int row = row0 + r;
        int col = col0 + (c4 << 2);
        if (EPI == 0) {
            if (bias) { v.x += bias[col]; v.y += bias[col+1]; v.z += bias[col+2]; v.w += bias[col+3]; }
            *(float4*)(C + (long)row*ldc + col) = cvt4(v);
        } else if (EPI == 1) {
            int pos = row;
            int y = pos >> 6, xq = pos & 63;
            int bb_ = (int)(z / 3), g = (int)(z % 3);
            int bwn = (bb_*2 + (y>>5))*2 + (xq>>5);
            int t   = (y&31)*32 + (xq&31);
            int cc  = g*256 + col;
            float4 pb4 = *(const float4*)(g_pet + (long)pos*EDIM + cc);
            v.x += bias[cc+0] + pb4.x; v.y += bias[cc+1] + pb4.y;
            v.z += bias[cc+2] + pb4.z; v.w += bias[cc+3] + pb4.w;
            *(float4*)(g_rp + ((long)(bwn*LTOK + t))*EDIM + cc) = v;
        } else if (EPI == 2) {
            int oc = row, tok = col;
            int bb_ = tok >> 12, p = tok & 4095;
            float bia = bias[oc];
            v.x += bia; v.y += bia; v.z += bia; v.w += bia;
            *(float4*)(C + (long)bb_*(EDIM*4096) + (long)oc*4096 + p) = v;
        } else if (EPI == 3) {
            int bwn = (int)(z >> 3), h = (int)(z & 7);
            int t = row;
            int b_ = bwn >> 2, wy = (bwn >> 1) & 1, wx = bwn & 1;
            int ly = t >> 5, lx = t & 31;
            int tok = b_*4096 + (wy*32 + ly)*64 + (wx*32 + lx);
            *(float4*)(g_avt + (long)tok*EDIM + h*HDIM + (c4 << 2)) = cvt4(v);
        } else { // EPI 4
            const float* smG = sm + 2*STAGES*TB;
            int xi = row & 31, yi = row >> 5;
            float iq = sr[z*LTOK + row];
            float4 ib4 = *(const float4*)(sc + z*LTOK + col);
            int xj0 = col & 31, yj0 = col >> 5;
            v.x = (v.x + smG[xi - xj0     + 31] + smG[yi - yj0 + 31]) * iq * ib4.x;
            v.y = (v.y + smG[xi - (xj0+1) + 31] + smG[yi - yj0 + 31]) * iq * ib4.y;
            v.z = (v.z + smG[xi - (xj0+2) + 31] + smG[yi - yj0 + 31]) * iq * ib4.z;
            v.w = (v.w + smG[xi - (xj0+3) + 31] + smG[yi - yj0 + 31]) * iq * ib4.w;
            *(float4*)(C + (long)row*ldc + col) = cvt4(v);
        }
    }
}

// ---------------- host launch ----------------
static float* sym_addr(const void* sym) {
    void* p = nullptr;
    cudaGetSymbolAddress(&p, sym);
    return (float*)p;
}

extern "C" void kernel_launch(void* const* d_in, const int* in_sizes, int n_in,
                              void* d_out, int out_size) {
    const float* x      = (const float*)d_in[0];
    const float* ow     = (const float*)d_in[1];
    const float* obias  = (const float*)d_in[2];
    const float* rw     = (const float*)d_in[3];
    const float* rbias  = (const float*)d_in[4];
    const float* pe     = (const float*)d_in[5];
    const float* nb_g   = (const float*)d_in[6];
    const float* nb_b   = (const float*)d_in[7];
    const float* nq_g   = (const float*)d_in[8];
    const float* nq_b   = (const float*)d_in[9];
    const float* qw     = (const float*)d_in[10];
    const float* qb     = (const float*)d_in[11];
    const float* bw     = (const float*)d_in[12];
    const float* bb     = (const float*)d_in[13];
    const float* projw  = (const float*)d_in[14];
    const float* projb  = (const float*)d_in[15];

    float* out  = (float*)d_out;
    float* attn = out + OUT_ELEMS;

    float* p_rx  = sym_addr(g_rx);
    float* p_rpn = sym_addr(g_rpn);
    float* p_opn = sym_addr(g_opn);
    float* p_q   = sym_addr(g_q);
    float* p_bv  = sym_addr(g_bv);
    float* p_avt = sym_addr(g_avt);
    float* p_bvt = sym_addr(g_bvt);
    float* p_inq = sym_addr(g_inq);
    float* p_inb = sym_addr(g_inb);
    float* p_wq  = sym_addr(g_wq);
    float* p_wb  = sym_addr(g_wb);
    float* p_wp  = sym_addr(g_wp);
    float* p_wr  = sym_addr(g_wr);

    cudaFuncSetAttribute(tc_gemm<0,4>, cudaFuncAttributeMaxDynamicSharedMemorySize, SMEMSZ);
    cudaFuncSetAttribute(tc_gemm<1,4>, cudaFuncAttributeMaxDynamicSharedMemorySize, SMEMSZ);
    cudaFuncSetAttribute(tc_gemm<2,4>, cudaFuncAttributeMaxDynamicSharedMemorySize, SMEMSZ);
    cudaFuncSetAttribute(tc_gemm<3,3>, cudaFuncAttributeMaxDynamicSharedMemorySize, SMEMSZ);
    cudaFuncSetAttribute(tc_gemm<4,4>, cudaFuncAttributeMaxDynamicSharedMemorySize, SMEMSZ);

    k_cvtw<<<2304, 256>>>(qw, bw, projw, rw, ow);                      // 1
    k_tr_pe<<<dim3(24, 128), dim3(32, 8)>>>(pe);                       // 2
    k_resize<<<24576, 256>>>(x);                                       // 3
    k_conv_o<<<dim3(256, BATCHN), 768>>>(x, obias);                    // 4
    // resize conv as tf32 GEMM with fused im2col gather (M=4096,N=256,K=256)
    tc_gemm<1,4><<<dim3(2, 32, 6), 256, SMEMSZ>>>(p_rx, p_wr, rbias, nullptr,
                                                  256, 256, 256, 0,
                                                  0, 0, 0, nullptr, nullptr);   // 5
    k_ln<<<dim3(BWIN*LTOK, 2), 256>>>(nb_g, nb_b, nq_g, nq_b);         // 6
    tc_gemm<0,4><<<dim3(6, 64, 1), 256, SMEMSZ>>>(p_rpn, p_wq, qb, p_q,
                                                  EDIM, EDIM, EDIM, EDIM, 0, 0, 0,
                                                  nullptr, nullptr);   // 7
    tc_gemm<0,4><<<dim3(6, 64, 1), 256, SMEMSZ>>>(p_opn, p_wb, bb, p_bv,
                                                  EDIM, EDIM, EDIM, EDIM, 0, 0, 0,
                                                  nullptr, nullptr);   // 8
    k_gtab<<<1, 64>>>();                                               // 9
    k_norm<<<dim3(BWIN*NHEADS, 2), 256>>>();                           // 10
    k_tr_bv<<<dim3(3, 32, 64), dim3(32, 8)>>>();                       // 11
    // attn = (q96·b96 + G) * inq * inb -> second output region
    tc_gemm<4,4><<<dim3(8, 8, BWIN*NHEADS), 256, SMEMSZ>>>(p_q, p_bv, nullptr, attn,
                                                           HDIM, EDIM, EDIM, LTOK,
                                                           0, 0, (long)LTOK*LTOK,
                                                           p_inq, p_inb);       // 12
    // av = attn @ b (N=96 exact) -> g_avt
    tc_gemm<3,3><<<dim3(1, 8, BWIN*NHEADS), 256, SMEMSZ>>>(attn, p_bvt, nullptr, nullptr,
                                                           LTOK, LTOK, LTOK, 0,
                                                           (long)LTOK*LTOK, (long)HDIM*LTOK, 0,
                                                           nullptr, nullptr);   // 13
    // final projection -> first output region
    tc_gemm<2,4><<<dim3(64, 6, 1), 256, SMEMSZ>>>(p_wp, p_avt, projb, out,
                                                  EDIM, EDIM, EDIM, 0, 0, 0, 0,
                                                  nullptr, nullptr);   // 14
}